// round 2
// baseline (speedup 1.0000x reference)
#include <cuda_runtime.h>

// Problem constants
#define BATCH  256
#define SEQ    100
#define CH     512
#define MTOT   (BATCH*SEQ)     // 25600
#define DIMIN  2048
#define LAYERS 6

// GEMM tile config
#define BM 128
#define BN 128
#define BK 8
#define SPAD 4

// ---------------------------------------------------------------------------
// Scratch (device globals: allocation inside kernel_launch is forbidden)
// ---------------------------------------------------------------------------
__device__ float g_X [MTOT*CH];
__device__ float g_G [MTOT*CH];
__device__ float g_TH[MTOT*CH];
__device__ float g_PH[MTOT*CH];
__device__ float g_R [BATCH*SEQ*SEQ];
__device__ float g_Y [MTOT*CH];

// ---------------------------------------------------------------------------
// Packed fp32x2 helpers (FFMA2 path: 2 FMAs per issued instruction)
// ---------------------------------------------------------------------------
__device__ __forceinline__ unsigned long long packf2(float lo, float hi){
    unsigned long long d;
    asm("mov.b64 %0, {%1, %2};" : "=l"(d) : "f"(lo), "f"(hi));
    return d;
}
__device__ __forceinline__ float2 unpackf2(unsigned long long v){
    float2 r;
    asm("mov.b64 {%0, %1}, %2;" : "=f"(r.x), "=f"(r.y) : "l"(v));
    return r;
}
__device__ __forceinline__ void fma2(unsigned long long &acc,
                                     unsigned long long a,
                                     unsigned long long b){
    asm("fma.rn.f32x2 %0, %1, %2, %0;" : "+l"(acc) : "l"(a), "l"(b));
}

// Shared inner-product step: 8 k-steps of the 8x8 microtile in f32x2.
// acc[i][j] holds output columns (tx*8 + 2j, tx*8 + 2j + 1) for row ty*8+i.
__device__ __forceinline__ void mm_step(
    const float (&As)[BK][BM+SPAD], const float (&Bs)[BK][BN+SPAD],
    int tx, int ty, unsigned long long (&acc)[8][4])
{
    #pragma unroll
    for (int k = 0; k < BK; k++){
        float4 a0 = *(const float4*)&As[k][ty*8];
        float4 a1 = *(const float4*)&As[k][ty*8+4];
        float4 b0 = *(const float4*)&Bs[k][tx*8];
        float4 b1 = *(const float4*)&Bs[k][tx*8+4];
        unsigned long long bp[4];
        bp[0] = packf2(b0.x, b0.y);
        bp[1] = packf2(b0.z, b0.w);
        bp[2] = packf2(b1.x, b1.y);
        bp[3] = packf2(b1.z, b1.w);
        float av[8] = {a0.x,a0.y,a0.z,a0.w,a1.x,a1.y,a1.z,a1.w};
        #pragma unroll
        for (int i = 0; i < 8; i++){
            unsigned long long ap = packf2(av[i], av[i]);
            fma2(acc[i][0], ap, bp[0]);
            fma2(acc[i][1], ap, bp[1]);
            fma2(acc[i][2], ap, bp[2]);
            fma2(acc[i][3], ap, bp[3]);
        }
    }
}

// ---------------------------------------------------------------------------
// Main TN GEMM: C[m,n] = sum_k A[m,k]*B[n,k]  (both operands K-major)
// MODE 0: + bias[n]
// MODE 1: out = resid + (acc + bias - mean) * (gamma*rsqrt(var+eps)) + beta
// Requires: M % BM == 0, N % BN == 0, K % BK == 0, lda/ldb % 4 == 0.
// ---------------------------------------------------------------------------
template<int MODE>
__global__ __launch_bounds__(256, 2)
void gemm_tn(const float* __restrict__ A, int lda,
             const float* __restrict__ B, int ldb,
             float* __restrict__ C, int ldc, int K,
             const float* __restrict__ bias,
             const float* __restrict__ resid,
             const float* __restrict__ gamma,
             const float* __restrict__ beta,
             const float* __restrict__ mean,
             const float* __restrict__ var)
{
    __shared__ float As[BK][BM+SPAD];
    __shared__ float Bs[BK][BN+SPAD];
    int tid = threadIdx.x;
    int tx = tid & 15, ty = tid >> 4;
    int m0 = blockIdx.y * BM;
    int n0 = blockIdx.x * BN;
    int lrow = tid >> 1;
    int lcol = (tid & 1) << 2;
    const float* Ap = A + (size_t)(m0 + lrow) * lda + lcol;
    const float* Bp = B + (size_t)(n0 + lrow) * ldb + lcol;

    unsigned long long acc[8][4];
    #pragma unroll
    for (int i = 0; i < 8; i++)
        #pragma unroll
        for (int j = 0; j < 4; j++) acc[i][j] = 0ull;

    for (int k0 = 0; k0 < K; k0 += BK){
        float4 a = *(const float4*)(Ap + k0);
        float4 b = *(const float4*)(Bp + k0);
        __syncthreads();
        As[lcol+0][lrow]=a.x; As[lcol+1][lrow]=a.y;
        As[lcol+2][lrow]=a.z; As[lcol+3][lrow]=a.w;
        Bs[lcol+0][lrow]=b.x; Bs[lcol+1][lrow]=b.y;
        Bs[lcol+2][lrow]=b.z; Bs[lcol+3][lrow]=b.w;
        __syncthreads();
        mm_step(As, Bs, tx, ty, acc);
    }

    int cbase = n0 + tx*8;
    float scale[8], shift[8];
    #pragma unroll
    for (int j = 0; j < 8; j++){
        int c = cbase + j;
        if (MODE == 0){
            scale[j] = 1.0f;
            shift[j] = bias[c];
        } else {
            float iv = gamma[c] * rsqrtf(var[c] + 1e-5f);
            scale[j] = iv;
            shift[j] = (bias[c] - mean[c]) * iv + beta[c];
        }
    }
    #pragma unroll
    for (int i = 0; i < 8; i++){
        int m = m0 + ty*8 + i;
        float* Co = C + (size_t)m * ldc + cbase;
        const float* Rr = (MODE == 1) ? (resid + (size_t)m * CH + cbase) : nullptr;
        #pragma unroll
        for (int j = 0; j < 4; j++){
            float2 v = unpackf2(acc[i][j]);
            float o0 = v.x * scale[2*j]   + shift[2*j];
            float o1 = v.y * scale[2*j+1] + shift[2*j+1];
            if (MODE == 1){ o0 += Rr[2*j]; o1 += Rr[2*j+1]; }
            *(float2*)(Co + 2*j) = make_float2(o0, o1);
        }
    }
}

// ---------------------------------------------------------------------------
// R[b,n,m] = (1/SEQ) * sum_i TH[b,n,i] * PH[b,m,i]   (TN, 100x100x512)
// One block per batch; 128x128 tile covers the 100x100 output.
// ---------------------------------------------------------------------------
__global__ __launch_bounds__(256, 2)
void attn_r()
{
    int b = blockIdx.x;
    const float* A  = g_TH + (size_t)b * SEQ * CH;
    const float* Bp = g_PH + (size_t)b * SEQ * CH;
    __shared__ float As[BK][BM+SPAD];
    __shared__ float Bs[BK][BN+SPAD];
    int tid = threadIdx.x;
    int tx = tid & 15, ty = tid >> 4;
    int lrow = tid >> 1;
    int lcol = (tid & 1) << 2;
    bool ok = lrow < SEQ;

    unsigned long long acc[8][4];
    #pragma unroll
    for (int i = 0; i < 8; i++)
        #pragma unroll
        for (int j = 0; j < 4; j++) acc[i][j] = 0ull;

    for (int k0 = 0; k0 < CH; k0 += BK){
        float4 a = ok ? *(const float4*)(A  + (size_t)lrow*CH + k0 + lcol)
                      : make_float4(0.f,0.f,0.f,0.f);
        float4 c = ok ? *(const float4*)(Bp + (size_t)lrow*CH + k0 + lcol)
                      : make_float4(0.f,0.f,0.f,0.f);
        __syncthreads();
        As[lcol+0][lrow]=a.x; As[lcol+1][lrow]=a.y;
        As[lcol+2][lrow]=a.z; As[lcol+3][lrow]=a.w;
        Bs[lcol+0][lrow]=c.x; Bs[lcol+1][lrow]=c.y;
        Bs[lcol+2][lrow]=c.z; Bs[lcol+3][lrow]=c.w;
        __syncthreads();
        mm_step(As, Bs, tx, ty, acc);
    }

    float* Ro = g_R + (size_t)b * SEQ * SEQ;
    const float inv_n = 1.0f / (float)SEQ;
    #pragma unroll
    for (int i = 0; i < 8; i++){
        int m = ty*8 + i;
        if (m < SEQ){
            #pragma unroll
            for (int j = 0; j < 4; j++){
                float2 v = unpackf2(acc[i][j]);
                int n = tx*8 + 2*j;
                if (n   < SEQ) Ro[m*SEQ + n]     = v.x * inv_n;
                if (n+1 < SEQ) Ro[m*SEQ + n + 1] = v.y * inv_n;
            }
        }
    }
}

// ---------------------------------------------------------------------------
// Y[b,n,i] = sum_m R[b,n,m] * G[b,m,i]   (NN, M=100, K=100, N=512)
// grid.x = CH/BN tiles, grid.y = batch
// ---------------------------------------------------------------------------
__global__ __launch_bounds__(256, 2)
void attn_y()
{
    int b  = blockIdx.y;
    int n0 = blockIdx.x * BN;
    const float* A  = g_R + (size_t)b * SEQ * SEQ;   // [100,100]
    const float* Bg = g_G + (size_t)b * SEQ * CH;    // [100,512], row = k
    __shared__ float As[BK][BM+SPAD];
    __shared__ float Bs[BK][BN+SPAD];
    int tid = threadIdx.x;
    int tx = tid & 15, ty = tid >> 4;
    int lrow = tid >> 1;            // A row (m)
    int lcol = (tid & 1) << 2;      // A k sub-offset
    int brow = tid >> 5;            // B k row (0..7)
    int bcol = (tid & 31) << 2;     // B col offset

    unsigned long long acc[8][4];
    #pragma unroll
    for (int i = 0; i < 8; i++)
        #pragma unroll
        for (int j = 0; j < 4; j++) acc[i][j] = 0ull;

    for (int k0 = 0; k0 < SEQ; k0 += BK){
        float av[4];
        #pragma unroll
        for (int j = 0; j < 4; j++){
            int kk = k0 + lcol + j;
            av[j] = (lrow < SEQ && kk < SEQ) ? A[lrow*SEQ + kk] : 0.0f;
        }
        int kb = k0 + brow;
        float4 bv = (kb < SEQ) ? *(const float4*)(Bg + (size_t)kb*CH + n0 + bcol)
                               : make_float4(0.f,0.f,0.f,0.f);
        __syncthreads();
        As[lcol+0][lrow]=av[0]; As[lcol+1][lrow]=av[1];
        As[lcol+2][lrow]=av[2]; As[lcol+3][lrow]=av[3];
        *(float4*)&Bs[brow][bcol] = bv;
        __syncthreads();
        mm_step(As, Bs, tx, ty, acc);
    }

    #pragma unroll
    for (int i = 0; i < 8; i++){
        int m = ty*8 + i;
        if (m < SEQ){
            float* Yo = g_Y + (size_t)(b*SEQ + m) * CH + n0 + tx*8;
            #pragma unroll
            for (int j = 0; j < 4; j++){
                float2 v = unpackf2(acc[i][j]);
                *(float2*)(Yo + 2*j) = make_float2(v.x, v.y);
            }
        }
    }
}

// ---------------------------------------------------------------------------
// Launch
// ---------------------------------------------------------------------------
extern "C" void kernel_launch(void* const* d_in, const int* in_sizes, int n_in,
                              void* d_out, int out_size)
{
    (void)in_sizes; (void)n_in; (void)out_size;
    const float* img      = (const float*)d_in[0];
    const float* trans_w  = (const float*)d_in[1];
    const float* trans_b  = (const float*)d_in[2];
    const float* gw       = (const float*)d_in[3];
    const float* gb       = (const float*)d_in[4];
    const float* tw       = (const float*)d_in[5];
    const float* tb       = (const float*)d_in[6];
    const float* pw       = (const float*)d_in[7];
    const float* pb       = (const float*)d_in[8];
    const float* ww       = (const float*)d_in[9];
    const float* wb       = (const float*)d_in[10];
    const float* bn_gamma = (const float*)d_in[11];
    const float* bn_beta  = (const float*)d_in[12];
    const float* bn_mean  = (const float*)d_in[13];
    const float* bn_var   = (const float*)d_in[14];
    float* out = (float*)d_out;

    float *X, *G, *TH, *PH, *Y;
    cudaGetSymbolAddress((void**)&X,  g_X);
    cudaGetSymbolAddress((void**)&G,  g_G);
    cudaGetSymbolAddress((void**)&TH, g_TH);
    cudaGetSymbolAddress((void**)&PH, g_PH);
    cudaGetSymbolAddress((void**)&Y,  g_Y);

    dim3 thr(256);
    dim3 grid_big(CH/BN, MTOT/BM);   // (4, 200)

    // Encoder: X = img @ trans_w^T + trans_b
    gemm_tn<0><<<grid_big, thr>>>(img, DIMIN, trans_w, DIMIN, X, CH, DIMIN,
                                  trans_b, nullptr, nullptr, nullptr, nullptr, nullptr);

    for (int l = 0; l < LAYERS; l++){
        const float* gwl = gw + (size_t)l*CH*CH;
        const float* twl = tw + (size_t)l*CH*CH;
        const float* pwl = pw + (size_t)l*CH*CH;
        const float* wwl = ww + (size_t)l*CH*CH;
        const float* gbl = gb + (size_t)l*CH;
        const float* tbl = tb + (size_t)l*CH;
        const float* pbl = pb + (size_t)l*CH;
        const float* wbl = wb + (size_t)l*CH;

        gemm_tn<0><<<grid_big, thr>>>(X, CH, gwl, CH, G,  CH, CH,
                                      gbl, nullptr, nullptr, nullptr, nullptr, nullptr);
        gemm_tn<0><<<grid_big, thr>>>(X, CH, twl, CH, TH, CH, CH,
                                      tbl, nullptr, nullptr, nullptr, nullptr, nullptr);
        gemm_tn<0><<<grid_big, thr>>>(X, CH, pwl, CH, PH, CH, CH,
                                      pbl, nullptr, nullptr, nullptr, nullptr, nullptr);

        attn_r<<<BATCH, thr>>>();
        attn_y<<<dim3(CH/BN, BATCH), thr>>>();

        float* o = (l == LAYERS-1) ? out : X;
        gemm_tn<1><<<grid_big, thr>>>(Y, CH, wwl, CH, o, CH, CH,
                                      wbl, X,
                                      bn_gamma + (size_t)l*CH,
                                      bn_beta  + (size_t)l*CH,
                                      bn_mean  + (size_t)l*CH,
                                      bn_var   + (size_t)l*CH);
    }
}

// round 4
// speedup vs baseline: 2.0375x; 2.0375x over previous
#include <cuda_runtime.h>
#include <cuda_bf16.h>
#include <cstdint>

#define BATCH  256
#define SEQ    100
#define CH     512
#define MTOT   (BATCH*SEQ)
#define DIMIN  2048
#define LAYERS 6
typedef __nv_bfloat16 bf16;
typedef unsigned long long u64;

// ---------------- scratch ----------------
__device__ float g_X [MTOT*CH];
__device__ float g_G [MTOT*CH];
__device__ float g_TH[MTOT*CH];
__device__ float g_PH[MTOT*CH];
__device__ float g_R [BATCH*SEQ*SEQ];
__device__ bf16  g_Xh[MTOT*CH], g_Xl[MTOT*CH];
__device__ bf16  g_Yh[MTOT*CH], g_Yl[MTOT*CH];
__device__ bf16  g_Ih[MTOT*DIMIN], g_Il[MTOT*DIMIN];

#define WOFF_TRANS 0
#define WSZ_TRANS  (CH*DIMIN)
#define WSZ_LCC    (LAYERS*CH*CH)
#define WOFF_G     (WOFF_TRANS + WSZ_TRANS)
#define WOFF_T     (WOFF_G + WSZ_LCC)
#define WOFF_P     (WOFF_T + WSZ_LCC)
#define WOFF_W     (WOFF_P + WSZ_LCC)
#define WTOT       (WOFF_W + WSZ_LCC)
__device__ bf16 g_Wh[WTOT], g_Wl[WTOT];

// ---------------- helpers ----------------
__device__ __forceinline__ uint32_t smem_u32(const void* p){
    uint32_t a;
    asm("{ .reg .u64 t; cvta.to.shared.u64 t, %1; cvt.u32.u64 %0, t; }" : "=r"(a) : "l"(p));
    return a;
}
__device__ __forceinline__ void ldsm4(uint32_t &r0, uint32_t &r1, uint32_t &r2, uint32_t &r3, uint32_t a){
    asm volatile("ldmatrix.sync.aligned.m8n8.x4.shared.b16 {%0,%1,%2,%3}, [%4];"
        : "=r"(r0), "=r"(r1), "=r"(r2), "=r"(r3) : "r"(a));
}
__device__ __forceinline__ void mma16816(float* c, const uint32_t* a, const uint32_t* b){
    asm volatile("mma.sync.aligned.m16n8k16.row.col.f32.bf16.bf16.f32 "
        "{%0,%1,%2,%3}, {%4,%5,%6,%7}, {%8,%9}, {%0,%1,%2,%3};"
        : "+f"(c[0]), "+f"(c[1]), "+f"(c[2]), "+f"(c[3])
        : "r"(a[0]), "r"(a[1]), "r"(a[2]), "r"(a[3]), "r"(b[0]), "r"(b[1]));
}
#define CP16(dst, src) asm volatile("cp.async.cg.shared.global [%0], [%1], 16;" :: "r"(dst), "l"(src))
#define CPCOMMIT()     asm volatile("cp.async.commit_group;" ::: "memory")
#define CPWAIT(n)      asm volatile("cp.async.wait_group %0;" :: "n"(n) : "memory")

__device__ __forceinline__ void split1(float v, bf16 &h, bf16 &l){
    h = __float2bfloat16(v);
    l = __float2bfloat16(v - __bfloat162float(h));
}

// ---------------- bf16x3 mma GEMM ----------------
// C[m,n] = sum_k A[m,k]*B[n,k]. Tile 128x128, BK=32, 3-stage cp.async.
// MODE 0: +bias | 1: +bias,+split | 2: BN+resid,+split | 3: BN+resid
#define STAGES 3
#define STG_B  32768
#define SMEM_DYN (STAGES*STG_B)

template<int MODE>
__global__ __launch_bounds__(256, 1)
void mma_gemm(const bf16* __restrict__ Ah, const bf16* __restrict__ Al,
              const bf16* __restrict__ Bh, const bf16* __restrict__ Bl,
              int K, float* out, bf16* outh, bf16* outl,
              const float* __restrict__ bias, const float* resid,
              const float* __restrict__ gamma, const float* __restrict__ beta,
              const float* __restrict__ mean,  const float* __restrict__ var)
{
    extern __shared__ __align__(1024) char smem[];
    uint32_t sb = smem_u32(smem);
    int tid = threadIdx.x, wid = tid >> 5, lane = tid & 31;
    int n0 = blockIdx.x * 128, m0 = blockIdx.y * 128;
    Ah += (size_t)m0 * K;  Al += (size_t)m0 * K;
    Bh += (size_t)n0 * K;  Bl += (size_t)n0 * K;

    float acc[2][8][4];
    #pragma unroll
    for (int i = 0; i < 2; i++)
        #pragma unroll
        for (int j = 0; j < 8; j++)
            #pragma unroll
            for (int q = 0; q < 4; q++) acc[i][j][q] = 0.f;

    // stage loader: hi/lo interleaved 128B rows, XOR-swizzled 16B chunks
    auto stage_load = [&](int slot, int k0){
        uint32_t base = sb + slot * STG_B;
        #pragma unroll
        for (int i = 0; i < 8; i++){
            int chunk = tid + i * 256;
            int tile = chunk >> 10;          // 0 = A, 1 = B
            int cid = chunk & 1023;
            int row = cid >> 3, ch = cid & 7;
            const bf16* hi = tile ? Bh : Ah;
            const bf16* lo = tile ? Bl : Al;
            const bf16* src = (ch < 4 ? hi : lo) + (size_t)row * K + k0 + (ch & 3) * 8;
            uint32_t dst = base + tile * 16384 + row * 128 + ((ch ^ (row & 7)) << 4);
            CP16(dst, src);
        }
    };

    const int kiters = K / 32;
    #pragma unroll
    for (int s = 0; s < STAGES - 1; s++){ stage_load(s, s * 32); CPCOMMIT(); }

    int wm = wid >> 1, wn = wid & 1;
    int g = lane >> 3, r = lane & 7;

    for (int it = 0; it < kiters; it++){
        CPWAIT(STAGES - 2);
        __syncthreads();
        uint32_t sA = sb + (it % STAGES) * STG_B;
        uint32_t sB = sA + 16384;
        #pragma unroll
        for (int kt = 0; kt < 2; kt++){
            uint32_t ah[2][4], al[2][4], bh[8][2], bl[8][2];
            #pragma unroll
            for (int mt = 0; mt < 2; mt++){
                int row = wm*32 + mt*16 + (g & 1)*8 + r;
                int sw = row & 7;
                uint32_t ra = sA + row * 128;
                int ch = kt*2 + (g >> 1);
                ldsm4(ah[mt][0], ah[mt][1], ah[mt][2], ah[mt][3], ra + ((ch ^ sw) << 4));
                ch += 4;
                ldsm4(al[mt][0], al[mt][1], al[mt][2], al[mt][3], ra + ((ch ^ sw) << 4));
            }
            #pragma unroll
            for (int np = 0; np < 4; np++){
                int row = wn*64 + np*16 + (g & 1)*8 + r;
                int sw = row & 7;
                uint32_t rb = sB + row * 128;
                uint32_t t0, t1, t2, t3;
                int ch = kt*2 + (g >> 1);
                ldsm4(t0, t1, t2, t3, rb + ((ch ^ sw) << 4));
                bh[2*np][0] = t0; bh[2*np+1][0] = t1; bh[2*np][1] = t2; bh[2*np+1][1] = t3;
                ch += 4;
                ldsm4(t0, t1, t2, t3, rb + ((ch ^ sw) << 4));
                bl[2*np][0] = t0; bl[2*np+1][0] = t1; bl[2*np][1] = t2; bl[2*np+1][1] = t3;
            }
            #pragma unroll
            for (int mt = 0; mt < 2; mt++)
                #pragma unroll
                for (int nt = 0; nt < 8; nt++){
                    mma16816(acc[mt][nt], ah[mt], bh[nt]);
                    mma16816(acc[mt][nt], ah[mt], bl[nt]);
                    mma16816(acc[mt][nt], al[mt], bh[nt]);
                }
        }
        if (it + STAGES - 1 < kiters)
            stage_load((it + STAGES - 1) % STAGES, (it + STAGES - 1) * 32);
        CPCOMMIT();
    }

    CPWAIT(0);
    __syncthreads();
    float* cs = (float*)smem;
    float* cf = cs + 128;
    if (tid < 128){
        int c = n0 + tid;
        if (MODE >= 2){
            float iv = gamma[c] * rsqrtf(var[c] + 1e-5f);
            cs[tid] = iv;
            cf[tid] = (bias[c] - mean[c]) * iv + beta[c];
        } else { cs[tid] = 1.0f; cf[tid] = bias[c]; }
    }
    __syncthreads();

    int q = lane >> 2, p = lane & 3;
    #pragma unroll
    for (int mt = 0; mt < 2; mt++)
        #pragma unroll
        for (int nt = 0; nt < 8; nt++){
            int c = wn*64 + nt*8 + 2*p;
            int gcol = n0 + c;
            #pragma unroll
            for (int h = 0; h < 2; h++){
                int row = m0 + wm*32 + mt*16 + q + h*8;
                float v0 = acc[mt][nt][2*h+0] * cs[c]   + cf[c];
                float v1 = acc[mt][nt][2*h+1] * cs[c+1] + cf[c+1];
                size_t off = (size_t)row * CH + gcol;
                if (MODE >= 2){
                    float2 rv = *(const float2*)(resid + off);
                    v0 += rv.x; v1 += rv.y;
                }
                *(float2*)(out + off) = make_float2(v0, v1);
                if (MODE == 1 || MODE == 2){
                    bf16 h0, l0, h1, l1;
                    split1(v0, h0, l0); split1(v1, h1, l1);
                    *(__nv_bfloat162*)(outh + off) = __nv_bfloat162(h0, h1);
                    *(__nv_bfloat162*)(outl + off) = __nv_bfloat162(l0, l1);
                }
            }
        }
}

// ---------------- bf16 split ----------------
__global__ void split_bf16(const float* __restrict__ in, bf16* __restrict__ hi,
                           bf16* __restrict__ lo, int n)
{
    int i = (blockIdx.x * blockDim.x + threadIdx.x) * 4;
    if (i < n){
        float4 x = *(const float4*)(in + i);
        bf16 h0,l0,h1,l1,h2,l2,h3,l3;
        split1(x.x,h0,l0); split1(x.y,h1,l1); split1(x.z,h2,l2); split1(x.w,h3,l3);
        *(__nv_bfloat162*)(hi + i)     = __nv_bfloat162(h0, h1);
        *(__nv_bfloat162*)(hi + i + 2) = __nv_bfloat162(h2, h3);
        *(__nv_bfloat162*)(lo + i)     = __nv_bfloat162(l0, l1);
        *(__nv_bfloat162*)(lo + i + 2) = __nv_bfloat162(l2, l3);
    }
}

// ---------------- SIMT attention (f32x2) ----------------
#define BM 128
#define BN 128
#define BK 8
#define SPAD 4
__device__ __forceinline__ u64 packf2(float lo, float hi){
    u64 d; asm("mov.b64 %0, {%1, %2};" : "=l"(d) : "f"(lo), "f"(hi)); return d;
}
__device__ __forceinline__ float2 unpackf2(u64 v){
    float2 r; asm("mov.b64 {%0, %1}, %2;" : "=f"(r.x), "=f"(r.y) : "l"(v)); return r;
}
__device__ __forceinline__ void fma2(u64 &acc, u64 a, u64 b){
    asm("fma.rn.f32x2 %0, %1, %2, %0;" : "+l"(acc) : "l"(a), "l"(b));
}
__device__ __forceinline__ void mm_step(
    const float (&As)[BK][BM+SPAD], const float (&Bs)[BK][BN+SPAD],
    int tx, int ty, u64 (&acc)[8][4])
{
    #pragma unroll
    for (int k = 0; k < BK; k++){
        float4 a0 = *(const float4*)&As[k][ty*8];
        float4 a1 = *(const float4*)&As[k][ty*8+4];
        float4 b0 = *(const float4*)&Bs[k][tx*8];
        float4 b1 = *(const float4*)&Bs[k][tx*8+4];
        u64 bp[4] = {packf2(b0.x,b0.y), packf2(b0.z,b0.w),
                     packf2(b1.x,b1.y), packf2(b1.z,b1.w)};
        float av[8] = {a0.x,a0.y,a0.z,a0.w,a1.x,a1.y,a1.z,a1.w};
        #pragma unroll
        for (int i = 0; i < 8; i++){
            u64 ap = packf2(av[i], av[i]);
            fma2(acc[i][0], ap, bp[0]);
            fma2(acc[i][1], ap, bp[1]);
            fma2(acc[i][2], ap, bp[2]);
            fma2(acc[i][3], ap, bp[3]);
        }
    }
}

__global__ __launch_bounds__(256, 2)
void attn_r()
{
    int b = blockIdx.x;
    const float* A  = g_TH + (size_t)b * SEQ * CH;
    const float* Bp = g_PH + (size_t)b * SEQ * CH;
    __shared__ float As[BK][BM+SPAD];
    __shared__ float Bs[BK][BN+SPAD];
    int tid = threadIdx.x;
    int tx = tid & 15, ty = tid >> 4;
    int lrow = tid >> 1, lcol = (tid & 1) << 2;
    bool ok = lrow < SEQ;
    u64 acc[8][4];
    #pragma unroll
    for (int i = 0; i < 8; i++)
        #pragma unroll
        for (int j = 0; j < 4; j++) acc[i][j] = 0ull;

    for (int k0 = 0; k0 < CH; k0 += BK){
        float4 a = ok ? *(const float4*)(A  + (size_t)lrow*CH + k0 + lcol) : make_float4(0,0,0,0);
        float4 c = ok ? *(const float4*)(Bp + (size_t)lrow*CH + k0 + lcol) : make_float4(0,0,0,0);
        __syncthreads();
        As[lcol+0][lrow]=a.x; As[lcol+1][lrow]=a.y; As[lcol+2][lrow]=a.z; As[lcol+3][lrow]=a.w;
        Bs[lcol+0][lrow]=c.x; Bs[lcol+1][lrow]=c.y; Bs[lcol+2][lrow]=c.z; Bs[lcol+3][lrow]=c.w;
        __syncthreads();
        mm_step(As, Bs, tx, ty, acc);
    }
    float* Ro = g_R + (size_t)b * SEQ * SEQ;
    const float inv_n = 1.0f / (float)SEQ;
    #pragma unroll
    for (int i = 0; i < 8; i++){
        int m = ty*8 + i;
        if (m < SEQ){
            #pragma unroll
            for (int j = 0; j < 4; j++){
                float2 v = unpackf2(acc[i][j]);
                int n = tx*8 + 2*j;
                if (n   < SEQ) Ro[m*SEQ + n]   = v.x * inv_n;
                if (n+1 < SEQ) Ro[m*SEQ + n+1] = v.y * inv_n;
            }
        }
    }
}

__global__ __launch_bounds__(256, 2)
void attn_y()
{
    int b  = blockIdx.y;
    int n0 = blockIdx.x * BN;
    const float* A  = g_R + (size_t)b * SEQ * SEQ;
    const float* Bg = g_G + (size_t)b * SEQ * CH;
    __shared__ float As[BK][BM+SPAD];
    __shared__ float Bs[BK][BN+SPAD];
    int tid = threadIdx.x;
    int tx = tid & 15, ty = tid >> 4;
    int lrow = tid >> 1, lcol = (tid & 1) << 2;
    int brow = tid >> 5, bcol = (tid & 31) << 2;
    u64 acc[8][4];
    #pragma unroll
    for (int i = 0; i < 8; i++)
        #pragma unroll
        for (int j = 0; j < 4; j++) acc[i][j] = 0ull;

    for (int k0 = 0; k0 < SEQ; k0 += BK){
        float av[4];
        #pragma unroll
        for (int j = 0; j < 4; j++){
            int kk = k0 + lcol + j;
            av[j] = (lrow < SEQ && kk < SEQ) ? A[lrow*SEQ + kk] : 0.0f;
        }
        int kb = k0 + brow;
        float4 bv = (kb < SEQ) ? *(const float4*)(Bg + (size_t)kb*CH + n0 + bcol)
                               : make_float4(0,0,0,0);
        __syncthreads();
        As[lcol+0][lrow]=av[0]; As[lcol+1][lrow]=av[1];
        As[lcol+2][lrow]=av[2]; As[lcol+3][lrow]=av[3];
        *(float4*)&Bs[brow][bcol] = bv;
        __syncthreads();
        mm_step(As, Bs, tx, ty, acc);
    }
    #pragma unroll
    for (int i = 0; i < 8; i++){
        int m = ty*8 + i;
        if (m < SEQ){
            size_t off = (size_t)(b*SEQ + m) * CH + n0 + tx*8;
            #pragma unroll
            for (int j = 0; j < 4; j++){
                float2 v = unpackf2(acc[i][j]);
                bf16 h0,l0,h1,l1;
                split1(v.x, h0, l0); split1(v.y, h1, l1);
                *(__nv_bfloat162*)(g_Yh + off + 2*j) = __nv_bfloat162(h0, h1);
                *(__nv_bfloat162*)(g_Yl + off + 2*j) = __nv_bfloat162(l0, l1);
            }
        }
    }
}

// ---------------- host ----------------
extern "C" void kernel_launch(void* const* d_in, const int* in_sizes, int n_in,
                              void* d_out, int out_size)
{
    (void)in_sizes; (void)n_in; (void)out_size;
    const float* img     = (const float*)d_in[0];
    const float* trans_w = (const float*)d_in[1];
    const float* trans_b = (const float*)d_in[2];
    const float* gw = (const float*)d_in[3];
    const float* gb = (const float*)d_in[4];
    const float* tw = (const float*)d_in[5];
    const float* tb = (const float*)d_in[6];
    const float* pw = (const float*)d_in[7];
    const float* pb = (const float*)d_in[8];
    const float* ww = (const float*)d_in[9];
    const float* wb = (const float*)d_in[10];
    const float* bn_gamma = (const float*)d_in[11];
    const float* bn_beta  = (const float*)d_in[12];
    const float* bn_mean  = (const float*)d_in[13];
    const float* bn_var   = (const float*)d_in[14];
    float* out = (float*)d_out;

    float *X, *G, *TH, *PH;
    bf16 *Xh, *Xl, *Yh, *Yl, *Ih, *Il, *Wh, *Wl;
    cudaGetSymbolAddress((void**)&X,  g_X);
    cudaGetSymbolAddress((void**)&G,  g_G);
    cudaGetSymbolAddress((void**)&TH, g_TH);
    cudaGetSymbolAddress((void**)&PH, g_PH);
    cudaGetSymbolAddress((void**)&Xh, g_Xh);
    cudaGetSymbolAddress((void**)&Xl, g_Xl);
    cudaGetSymbolAddress((void**)&Yh, g_Yh);
    cudaGetSymbolAddress((void**)&Yl, g_Yl);
    cudaGetSymbolAddress((void**)&Ih, g_Ih);
    cudaGetSymbolAddress((void**)&Il, g_Il);
    cudaGetSymbolAddress((void**)&Wh, g_Wh);
    cudaGetSymbolAddress((void**)&Wl, g_Wl);

    cudaFuncSetAttribute(mma_gemm<0>, cudaFuncAttributeMaxDynamicSharedMemorySize, SMEM_DYN);
    cudaFuncSetAttribute(mma_gemm<1>, cudaFuncAttributeMaxDynamicSharedMemorySize, SMEM_DYN);
    cudaFuncSetAttribute(mma_gemm<2>, cudaFuncAttributeMaxDynamicSharedMemorySize, SMEM_DYN);
    cudaFuncSetAttribute(mma_gemm<3>, cudaFuncAttributeMaxDynamicSharedMemorySize, SMEM_DYN);

    // bf16 splits of inputs
    {
        int n = MTOT*DIMIN;
        split_bf16<<<(n/4+255)/256, 256>>>(img, Ih, Il, n);
        n = WSZ_TRANS;
        split_bf16<<<(n/4+255)/256, 256>>>(trans_w, Wh+WOFF_TRANS, Wl+WOFF_TRANS, n);
        n = WSZ_LCC;
        split_bf16<<<(n/4+255)/256, 256>>>(gw, Wh+WOFF_G, Wl+WOFF_G, n);
        split_bf16<<<(n/4+255)/256, 256>>>(tw, Wh+WOFF_T, Wl+WOFF_T, n);
        split_bf16<<<(n/4+255)/256, 256>>>(pw, Wh+WOFF_P, Wl+WOFF_P, n);
        split_bf16<<<(n/4+255)/256, 256>>>(ww, Wh+WOFF_W, Wl+WOFF_W, n);
    }

    dim3 gmm(CH/128, MTOT/128);   // (4, 200)

    // encoder: X = img @ trans_w^T + b (+ bf16 split)
    mma_gemm<1><<<gmm, 256, SMEM_DYN>>>(Ih, Il, Wh+WOFF_TRANS, Wl+WOFF_TRANS, DIMIN,
        X, Xh, Xl, trans_b, nullptr, nullptr, nullptr, nullptr, nullptr);

    for (int l = 0; l < LAYERS; l++){
        size_t wo = (size_t)l*CH*CH;
        mma_gemm<0><<<gmm, 256, SMEM_DYN>>>(Xh, Xl, Wh+WOFF_G+wo, Wl+WOFF_G+wo, CH,
            G,  nullptr, nullptr, gb + l*CH, nullptr, nullptr, nullptr, nullptr, nullptr);
        mma_gemm<0><<<gmm, 256, SMEM_DYN>>>(Xh, Xl, Wh+WOFF_T+wo, Wl+WOFF_T+wo, CH,
            TH, nullptr, nullptr, tb + l*CH, nullptr, nullptr, nullptr, nullptr, nullptr);
        mma_gemm<0><<<gmm, 256, SMEM_DYN>>>(Xh, Xl, Wh+WOFF_P+wo, Wl+WOFF_P+wo, CH,
            PH, nullptr, nullptr, pb + l*CH, nullptr, nullptr, nullptr, nullptr, nullptr);

        attn_r<<<BATCH, 256>>>();
        attn_y<<<dim3(CH/BN, BATCH), 256>>>();

        if (l == LAYERS-1){
            mma_gemm<3><<<gmm, 256, SMEM_DYN>>>(Yh, Yl, Wh+WOFF_W+wo, Wl+WOFF_W+wo, CH,
                out, nullptr, nullptr, wb + l*CH, X,
                bn_gamma + l*CH, bn_beta + l*CH, bn_mean + l*CH, bn_var + l*CH);
        } else {
            mma_gemm<2><<<gmm, 256, SMEM_DYN>>>(Yh, Yl, Wh+WOFF_W+wo, Wl+WOFF_W+wo, CH,
                X, Xh, Xl, wb + l*CH, X,
                bn_gamma + l*CH, bn_beta + l*CH, bn_mean + l*CH, bn_var + l*CH);
        }
    }
}

// round 5
// speedup vs baseline: 2.2833x; 1.1206x over previous
#include <cuda_runtime.h>
#include <cuda_bf16.h>
#include <cstdint>

#define BATCH  256
#define SEQ    100
#define CH     512
#define MTOT   (BATCH*SEQ)
#define MPAD   (MTOT+28)
#define DIMIN  2048
#define LAYERS 6
typedef __nv_bfloat16 bf16;

// ---------------- scratch (zero-initialized device globals) ----------------
__device__ float g_X [MTOT*CH];
__device__ bf16  g_Xh[MTOT*CH], g_Xl[MTOT*CH];
__device__ bf16  g_Yh[MTOT*CH], g_Yl[MTOT*CH];
__device__ bf16  g_Ih[MTOT*DIMIN], g_Il[MTOT*DIMIN];
__device__ bf16  g_Gh[MPAD*CH],  g_Gl[MPAD*CH];
__device__ bf16  g_THh[MPAD*CH], g_THl[MPAD*CH];
__device__ bf16  g_PHh[MPAD*CH], g_PHl[MPAD*CH];
__device__ bf16  g_Rh[BATCH*128*128], g_Rl[BATCH*128*128];

#define WOFF_TRANS 0
#define WSZ_TRANS  (CH*DIMIN)
#define WSZ_LCC    (LAYERS*CH*CH)
#define WOFF_G     (WOFF_TRANS + WSZ_TRANS)
#define WOFF_T     (WOFF_G + WSZ_LCC)
#define WOFF_P     (WOFF_T + WSZ_LCC)
#define WOFF_W     (WOFF_P + WSZ_LCC)
#define WTOT       (WOFF_W + WSZ_LCC)
__device__ bf16 g_Wh[WTOT], g_Wl[WTOT];

// ---------------- helpers ----------------
__device__ __forceinline__ uint32_t smem_u32(const void* p){
    uint32_t a;
    asm("{ .reg .u64 t; cvta.to.shared.u64 t, %1; cvt.u32.u64 %0, t; }" : "=r"(a) : "l"(p));
    return a;
}
__device__ __forceinline__ void ldsm4(uint32_t &r0, uint32_t &r1, uint32_t &r2, uint32_t &r3, uint32_t a){
    asm volatile("ldmatrix.sync.aligned.m8n8.x4.shared.b16 {%0,%1,%2,%3}, [%4];"
        : "=r"(r0), "=r"(r1), "=r"(r2), "=r"(r3) : "r"(a));
}
__device__ __forceinline__ void ldsm4t(uint32_t &r0, uint32_t &r1, uint32_t &r2, uint32_t &r3, uint32_t a){
    asm volatile("ldmatrix.sync.aligned.m8n8.x4.trans.shared.b16 {%0,%1,%2,%3}, [%4];"
        : "=r"(r0), "=r"(r1), "=r"(r2), "=r"(r3) : "r"(a));
}
__device__ __forceinline__ void mma16816(float* c, const uint32_t* a, const uint32_t* b){
    asm volatile("mma.sync.aligned.m16n8k16.row.col.f32.bf16.bf16.f32 "
        "{%0,%1,%2,%3}, {%4,%5,%6,%7}, {%8,%9}, {%0,%1,%2,%3};"
        : "+f"(c[0]), "+f"(c[1]), "+f"(c[2]), "+f"(c[3])
        : "r"(a[0]), "r"(a[1]), "r"(a[2]), "r"(a[3]), "r"(b[0]), "r"(b[1]));
}
#define CP16(dst, src) asm volatile("cp.async.cg.shared.global [%0], [%1], 16;" :: "r"(dst), "l"(src))
#define CPCOMMIT()     asm volatile("cp.async.commit_group;" ::: "memory")
#define CPWAIT(n)      asm volatile("cp.async.wait_group %0;" :: "n"(n) : "memory")

__device__ __forceinline__ void split1(float v, bf16 &h, bf16 &l){
    h = __float2bfloat16(v);
    l = __float2bfloat16(v - __bfloat162float(h));
}

#define STAGES 3
#define STG_B  32768
#define SMEM_DYN (STAGES*STG_B)

// ---------------- bf16x3 mma GEMM (TN; A,B K-major pitch K) ----------------
// MODE 1: out fp32 = acc+bias, + split | MODE 2: BN+resid fp32, + split
// MODE 3: BN+resid fp32 only          | MODE 4: acc+bias, split only
template<int MODE>
__global__ __launch_bounds__(256, 1)
void mma_gemm(const bf16* __restrict__ Ah, const bf16* __restrict__ Al,
              const bf16* __restrict__ Bh, const bf16* __restrict__ Bl,
              int K, float* out, bf16* outh, bf16* outl,
              const float* __restrict__ bias, const float* resid,
              const float* __restrict__ gamma, const float* __restrict__ beta,
              const float* __restrict__ mean,  const float* __restrict__ var)
{
    extern __shared__ __align__(1024) char smem[];
    uint32_t sb = smem_u32(smem);
    int tid = threadIdx.x, wid = tid >> 5, lane = tid & 31;
    int n0 = blockIdx.x * 128, m0 = blockIdx.y * 128;
    Ah += (size_t)m0 * K;  Al += (size_t)m0 * K;
    Bh += (size_t)n0 * K;  Bl += (size_t)n0 * K;

    float acc[2][8][4];
    #pragma unroll
    for (int i = 0; i < 2; i++)
        #pragma unroll
        for (int j = 0; j < 8; j++)
            #pragma unroll
            for (int q = 0; q < 4; q++) acc[i][j][q] = 0.f;

    auto stage_load = [&](int slot, int k0){
        uint32_t base = sb + slot * STG_B;
        #pragma unroll
        for (int i = 0; i < 8; i++){
            int chunk = tid + i * 256;
            int tile = chunk >> 10;
            int cid = chunk & 1023;
            int row = cid >> 3, ch = cid & 7;
            const bf16* hi = tile ? Bh : Ah;
            const bf16* lo = tile ? Bl : Al;
            const bf16* src = (ch < 4 ? hi : lo) + (size_t)row * K + k0 + (ch & 3) * 8;
            uint32_t dst = base + tile * 16384 + row * 128 + ((ch ^ (row & 7)) << 4);
            CP16(dst, src);
        }
    };

    const int kiters = K / 32;
    #pragma unroll
    for (int s = 0; s < STAGES - 1; s++){ stage_load(s, s * 32); CPCOMMIT(); }

    int wm = wid >> 1, wn = wid & 1;
    int g = lane >> 3, r = lane & 7;

    for (int it = 0; it < kiters; it++){
        CPWAIT(STAGES - 2);
        __syncthreads();
        uint32_t sA = sb + (it % STAGES) * STG_B;
        uint32_t sB = sA + 16384;
        #pragma unroll
        for (int kt = 0; kt < 2; kt++){
            uint32_t ah[2][4], al[2][4], bh[8][2], bl[8][2];
            #pragma unroll
            for (int mt = 0; mt < 2; mt++){
                int row = wm*32 + mt*16 + (g & 1)*8 + r;
                int sw = row & 7;
                uint32_t ra = sA + row * 128;
                int ch = kt*2 + (g >> 1);
                ldsm4(ah[mt][0], ah[mt][1], ah[mt][2], ah[mt][3], ra + ((ch ^ sw) << 4));
                ch += 4;
                ldsm4(al[mt][0], al[mt][1], al[mt][2], al[mt][3], ra + ((ch ^ sw) << 4));
            }
            #pragma unroll
            for (int np = 0; np < 4; np++){
                int row = wn*64 + np*16 + (g & 1)*8 + r;
                int sw = row & 7;
                uint32_t rb = sB + row * 128;
                uint32_t t0, t1, t2, t3;
                int ch = kt*2 + (g >> 1);
                ldsm4(t0, t1, t2, t3, rb + ((ch ^ sw) << 4));
                bh[2*np][0] = t0; bh[2*np+1][0] = t1; bh[2*np][1] = t2; bh[2*np+1][1] = t3;
                ch += 4;
                ldsm4(t0, t1, t2, t3, rb + ((ch ^ sw) << 4));
                bl[2*np][0] = t0; bl[2*np+1][0] = t1; bl[2*np][1] = t2; bl[2*np+1][1] = t3;
            }
            #pragma unroll
            for (int mt = 0; mt < 2; mt++)
                #pragma unroll
                for (int nt = 0; nt < 8; nt++){
                    mma16816(acc[mt][nt], ah[mt], bh[nt]);
                    mma16816(acc[mt][nt], ah[mt], bl[nt]);
                    mma16816(acc[mt][nt], al[mt], bh[nt]);
                }
        }
        if (it + STAGES - 1 < kiters)
            stage_load((it + STAGES - 1) % STAGES, (it + STAGES - 1) * 32);
        CPCOMMIT();
    }

    CPWAIT(0);
    __syncthreads();
    float* cs = (float*)smem;
    float* cf = cs + 128;
    if (tid < 128){
        int c = n0 + tid;
        if (MODE == 2 || MODE == 3){
            float iv = gamma[c] * rsqrtf(var[c] + 1e-5f);
            cs[tid] = iv;
            cf[tid] = (bias[c] - mean[c]) * iv + beta[c];
        } else { cs[tid] = 1.0f; cf[tid] = bias[c]; }
    }
    __syncthreads();

    int q = lane >> 2, p = lane & 3;
    #pragma unroll
    for (int mt = 0; mt < 2; mt++)
        #pragma unroll
        for (int nt = 0; nt < 8; nt++){
            int c = wn*64 + nt*8 + 2*p;
            int gcol = n0 + c;
            #pragma unroll
            for (int h = 0; h < 2; h++){
                int row = m0 + wm*32 + mt*16 + q + h*8;
                float v0 = acc[mt][nt][2*h+0] * cs[c]   + cf[c];
                float v1 = acc[mt][nt][2*h+1] * cs[c+1] + cf[c+1];
                size_t off = (size_t)row * CH + gcol;
                if (MODE == 2 || MODE == 3){
                    float2 rv = *(const float2*)(resid + off);
                    v0 += rv.x; v1 += rv.y;
                }
                if (MODE != 4)
                    *(float2*)(out + off) = make_float2(v0, v1);
                if (MODE == 1 || MODE == 2 || MODE == 4){
                    bf16 h0, l0, h1, l1;
                    split1(v0, h0, l0); split1(v1, h1, l1);
                    *(__nv_bfloat162*)(outh + off) = __nv_bfloat162(h0, h1);
                    *(__nv_bfloat162*)(outl + off) = __nv_bfloat162(l0, l1);
                }
            }
        }
}

// ---------------- attn_r: R[b] = TH[b]·PH[b]^T / SEQ  (bf16x3 MMA) ----------
// One CTA per batch. Writes zero-padded 128x128 bf16 split R (pitch 128).
__global__ __launch_bounds__(256, 1)
void attn_r_mma()
{
    extern __shared__ __align__(1024) char smem[];
    uint32_t sb = smem_u32(smem);
    int tid = threadIdx.x, wid = tid >> 5, lane = tid & 31;
    int b = blockIdx.x;
    const bf16* Ah = g_THh + (size_t)b*SEQ*CH;
    const bf16* Al = g_THl + (size_t)b*SEQ*CH;
    const bf16* Bh = g_PHh + (size_t)b*SEQ*CH;
    const bf16* Bl = g_PHl + (size_t)b*SEQ*CH;

    float acc[2][8][4];
    #pragma unroll
    for (int i = 0; i < 2; i++)
        #pragma unroll
        for (int j = 0; j < 8; j++)
            #pragma unroll
            for (int q = 0; q < 4; q++) acc[i][j][q] = 0.f;

    auto stage_load = [&](int slot, int k0){
        uint32_t base = sb + slot * STG_B;
        #pragma unroll
        for (int i = 0; i < 8; i++){
            int chunk = tid + i * 256;
            int tile = chunk >> 10;
            int cid = chunk & 1023;
            int row = cid >> 3, ch = cid & 7;
            const bf16* hi = tile ? Bh : Ah;
            const bf16* lo = tile ? Bl : Al;
            const bf16* src = (ch < 4 ? hi : lo) + (size_t)row * CH + k0 + (ch & 3) * 8;
            uint32_t dst = base + tile * 16384 + row * 128 + ((ch ^ (row & 7)) << 4);
            CP16(dst, src);
        }
    };

    const int kiters = CH / 32;   // 16
    #pragma unroll
    for (int s = 0; s < STAGES - 1; s++){ stage_load(s, s * 32); CPCOMMIT(); }

    int wm = wid >> 1, wn = wid & 1;
    int g = lane >> 3, r = lane & 7;

    for (int it = 0; it < kiters; it++){
        CPWAIT(STAGES - 2);
        __syncthreads();
        uint32_t sA = sb + (it % STAGES) * STG_B;
        uint32_t sB = sA + 16384;
        #pragma unroll
        for (int kt = 0; kt < 2; kt++){
            uint32_t ah[2][4], al[2][4], bh[8][2], bl[8][2];
            #pragma unroll
            for (int mt = 0; mt < 2; mt++){
                int row = wm*32 + mt*16 + (g & 1)*8 + r;
                int sw = row & 7;
                uint32_t ra = sA + row * 128;
                int ch = kt*2 + (g >> 1);
                ldsm4(ah[mt][0], ah[mt][1], ah[mt][2], ah[mt][3], ra + ((ch ^ sw) << 4));
                ch += 4;
                ldsm4(al[mt][0], al[mt][1], al[mt][2], al[mt][3], ra + ((ch ^ sw) << 4));
            }
            #pragma unroll
            for (int np = 0; np < 4; np++){
                int row = wn*64 + np*16 + (g & 1)*8 + r;
                int sw = row & 7;
                uint32_t rb = sB + row * 128;
                uint32_t t0, t1, t2, t3;
                int ch = kt*2 + (g >> 1);
                ldsm4(t0, t1, t2, t3, rb + ((ch ^ sw) << 4));
                bh[2*np][0] = t0; bh[2*np+1][0] = t1; bh[2*np][1] = t2; bh[2*np+1][1] = t3;
                ch += 4;
                ldsm4(t0, t1, t2, t3, rb + ((ch ^ sw) << 4));
                bl[2*np][0] = t0; bl[2*np+1][0] = t1; bl[2*np][1] = t2; bl[2*np+1][1] = t3;
            }
            #pragma unroll
            for (int mt = 0; mt < 2; mt++)
                #pragma unroll
                for (int nt = 0; nt < 8; nt++){
                    mma16816(acc[mt][nt], ah[mt], bh[nt]);
                    mma16816(acc[mt][nt], ah[mt], bl[nt]);
                    mma16816(acc[mt][nt], al[mt], bh[nt]);
                }
        }
        if (it + STAGES - 1 < kiters)
            stage_load((it + STAGES - 1) % STAGES, (it + STAGES - 1) * 32);
        CPCOMMIT();
    }
    CPWAIT(0);

    const float inv_n = 1.0f / (float)SEQ;
    int q = lane >> 2, p = lane & 3;
    bf16* Rh = g_Rh + (size_t)b * 16384;
    bf16* Rl = g_Rl + (size_t)b * 16384;
    #pragma unroll
    for (int mt = 0; mt < 2; mt++)
        #pragma unroll
        for (int nt = 0; nt < 8; nt++){
            int c = wn*64 + nt*8 + 2*p;
            #pragma unroll
            for (int h = 0; h < 2; h++){
                int row = wm*32 + mt*16 + q + h*8;
                bool okr = row < SEQ;
                float v0 = (okr && c   < SEQ) ? acc[mt][nt][2*h+0] * inv_n : 0.f;
                float v1 = (okr && c+1 < SEQ) ? acc[mt][nt][2*h+1] * inv_n : 0.f;
                bf16 h0, l0, h1, l1;
                split1(v0, h0, l0); split1(v1, h1, l1);
                size_t off = (size_t)row * 128 + c;
                *(__nv_bfloat162*)(Rh + off) = __nv_bfloat162(h0, h1);
                *(__nv_bfloat162*)(Rl + off) = __nv_bfloat162(l0, l1);
            }
        }
}

// ---------------- attn_y: Y[b] = R[b]·G[b]  (NN via ldmatrix.trans) --------
// A = R split (K-major pitch 128, K=128 zero-padded). B = G split row-major.
__global__ __launch_bounds__(256, 1)
void attn_y_mma()
{
    extern __shared__ __align__(1024) char smem[];
    uint32_t sb = smem_u32(smem);
    int tid = threadIdx.x, wid = tid >> 5, lane = tid & 31;
    int b = blockIdx.y, n0 = blockIdx.x * 128;

    float acc[2][8][4];
    #pragma unroll
    for (int i = 0; i < 2; i++)
        #pragma unroll
        for (int j = 0; j < 8; j++)
            #pragma unroll
            for (int q = 0; q < 4; q++) acc[i][j][q] = 0.f;

    // stage: R region 16KB (128 rows x [4 hi + 4 lo] 16B chunks),
    //        G region 16KB (hi 32x256B @ +16384, lo @ +24576)
    auto stage_load = [&](int slot, int k0){
        uint32_t base = sb + slot * STG_B;
        #pragma unroll
        for (int i = 0; i < 4; i++){
            int cid = tid + i * 256;
            int row = cid >> 3, ch = cid & 7;
            const bf16* src = (ch < 4 ? g_Rh : g_Rl)
                + (size_t)b * 16384 + row * 128 + k0 + (ch & 3) * 8;
            uint32_t dst = base + row * 128 + ((ch ^ (row & 7)) << 4);
            CP16(dst, src);
        }
        #pragma unroll
        for (int i = 0; i < 4; i++){
            int cid = tid + i * 256;
            int buf = cid >> 9, rem = cid & 511;
            int k = rem >> 4, c = rem & 15;
            const bf16* src = (buf ? g_Gl : g_Gh)
                + (size_t)(b * SEQ + k0 + k) * CH + n0 + c * 8;
            uint32_t dst = base + 16384 + buf * 8192 + k * 256 + ((c ^ (k & 7)) << 4);
            CP16(dst, src);
        }
    };

    const int kiters = 4;   // K = 128
    #pragma unroll
    for (int s = 0; s < STAGES - 1; s++){ stage_load(s, s * 32); CPCOMMIT(); }

    int wm = wid >> 1, wn = wid & 1;
    int g = lane >> 3, r = lane & 7;
    int m = lane >> 3;

    for (int it = 0; it < kiters; it++){
        CPWAIT(STAGES - 2);
        __syncthreads();
        uint32_t sA = sb + (it % STAGES) * STG_B;
        uint32_t sG = sA + 16384;
        #pragma unroll
        for (int kt = 0; kt < 2; kt++){
            uint32_t ah[2][4], al[2][4], bh[8][2], bl[8][2];
            #pragma unroll
            for (int mt = 0; mt < 2; mt++){
                int row = wm*32 + mt*16 + (g & 1)*8 + r;
                int sw = row & 7;
                uint32_t ra = sA + row * 128;
                int ch = kt*2 + (g >> 1);
                ldsm4(ah[mt][0], ah[mt][1], ah[mt][2], ah[mt][3], ra + ((ch ^ sw) << 4));
                ch += 4;
                ldsm4(al[mt][0], al[mt][1], al[mt][2], al[mt][3], ra + ((ch ^ sw) << 4));
            }
            int krow = kt*16 + (lane & 7) + (m & 1)*8;
            int ksw = krow & 7;
            #pragma unroll
            for (int np = 0; np < 4; np++){
                int cb = wn*8 + np*2 + (m >> 1);
                uint32_t t0, t1, t2, t3;
                ldsm4t(t0, t1, t2, t3, sG + krow*256 + ((cb ^ ksw) << 4));
                bh[2*np][0] = t0; bh[2*np][1] = t1; bh[2*np+1][0] = t2; bh[2*np+1][1] = t3;
                ldsm4t(t0, t1, t2, t3, sG + 8192 + krow*256 + ((cb ^ ksw) << 4));
                bl[2*np][0] = t0; bl[2*np][1] = t1; bl[2*np+1][0] = t2; bl[2*np+1][1] = t3;
            }
            #pragma unroll
            for (int mt = 0; mt < 2; mt++)
                #pragma unroll
                for (int nt = 0; nt < 8; nt++){
                    mma16816(acc[mt][nt], ah[mt], bh[nt]);
                    mma16816(acc[mt][nt], ah[mt], bl[nt]);
                    mma16816(acc[mt][nt], al[mt], bh[nt]);
                }
        }
        if (it + STAGES - 1 < kiters)
            stage_load((it + STAGES - 1) % STAGES, (it + STAGES - 1) * 32);
        CPCOMMIT();
    }
    CPWAIT(0);

    int q = lane >> 2, p = lane & 3;
    #pragma unroll
    for (int mt = 0; mt < 2; mt++)
        #pragma unroll
        for (int nt = 0; nt < 8; nt++){
            int c = wn*64 + nt*8 + 2*p;
            #pragma unroll
            for (int h = 0; h < 2; h++){
                int row = wm*32 + mt*16 + q + h*8;
                if (row < SEQ){
                    float v0 = acc[mt][nt][2*h+0];
                    float v1 = acc[mt][nt][2*h+1];
                    bf16 h0, l0, h1, l1;
                    split1(v0, h0, l0); split1(v1, h1, l1);
                    size_t off = (size_t)(b*SEQ + row) * CH + n0 + c;
                    *(__nv_bfloat162*)(g_Yh + off) = __nv_bfloat162(h0, h1);
                    *(__nv_bfloat162*)(g_Yl + off) = __nv_bfloat162(l0, l1);
                }
            }
        }
}

// ---------------- bf16 split ----------------
__global__ void split_bf16(const float* __restrict__ in, bf16* __restrict__ hi,
                           bf16* __restrict__ lo, int n)
{
    int i = (blockIdx.x * blockDim.x + threadIdx.x) * 4;
    if (i < n){
        float4 x = *(const float4*)(in + i);
        bf16 h0,l0,h1,l1,h2,l2,h3,l3;
        split1(x.x,h0,l0); split1(x.y,h1,l1); split1(x.z,h2,l2); split1(x.w,h3,l3);
        *(__nv_bfloat162*)(hi + i)     = __nv_bfloat162(h0, h1);
        *(__nv_bfloat162*)(hi + i + 2) = __nv_bfloat162(h2, h3);
        *(__nv_bfloat162*)(lo + i)     = __nv_bfloat162(l0, l1);
        *(__nv_bfloat162*)(lo + i + 2) = __nv_bfloat162(l2, l3);
    }
}

// ---------------- host ----------------
extern "C" void kernel_launch(void* const* d_in, const int* in_sizes, int n_in,
                              void* d_out, int out_size)
{
    (void)in_sizes; (void)n_in; (void)out_size;
    const float* img     = (const float*)d_in[0];
    const float* trans_w = (const float*)d_in[1];
    const float* trans_b = (const float*)d_in[2];
    const float* gw = (const float*)d_in[3];
    const float* gb = (const float*)d_in[4];
    const float* tw = (const float*)d_in[5];
    const float* tb = (const float*)d_in[6];
    const float* pw = (const float*)d_in[7];
    const float* pb = (const float*)d_in[8];
    const float* ww = (const float*)d_in[9];
    const float* wb = (const float*)d_in[10];
    const float* bn_gamma = (const float*)d_in[11];
    const float* bn_beta  = (const float*)d_in[12];
    const float* bn_mean  = (const float*)d_in[13];
    const float* bn_var   = (const float*)d_in[14];
    float* out = (float*)d_out;

    float *X;
    bf16 *Xh, *Xl, *Yh, *Yl, *Ih, *Il, *Wh, *Wl, *Gh, *Gl, *THh, *THl, *PHh, *PHl;
    cudaGetSymbolAddress((void**)&X,   g_X);
    cudaGetSymbolAddress((void**)&Xh,  g_Xh);
    cudaGetSymbolAddress((void**)&Xl,  g_Xl);
    cudaGetSymbolAddress((void**)&Yh,  g_Yh);
    cudaGetSymbolAddress((void**)&Yl,  g_Yl);
    cudaGetSymbolAddress((void**)&Ih,  g_Ih);
    cudaGetSymbolAddress((void**)&Il,  g_Il);
    cudaGetSymbolAddress((void**)&Wh,  g_Wh);
    cudaGetSymbolAddress((void**)&Wl,  g_Wl);
    cudaGetSymbolAddress((void**)&Gh,  g_Gh);
    cudaGetSymbolAddress((void**)&Gl,  g_Gl);
    cudaGetSymbolAddress((void**)&THh, g_THh);
    cudaGetSymbolAddress((void**)&THl, g_THl);
    cudaGetSymbolAddress((void**)&PHh, g_PHh);
    cudaGetSymbolAddress((void**)&PHl, g_PHl);

    cudaFuncSetAttribute(mma_gemm<1>, cudaFuncAttributeMaxDynamicSharedMemorySize, SMEM_DYN);
    cudaFuncSetAttribute(mma_gemm<2>, cudaFuncAttributeMaxDynamicSharedMemorySize, SMEM_DYN);
    cudaFuncSetAttribute(mma_gemm<3>, cudaFuncAttributeMaxDynamicSharedMemorySize, SMEM_DYN);
    cudaFuncSetAttribute(mma_gemm<4>, cudaFuncAttributeMaxDynamicSharedMemorySize, SMEM_DYN);
    cudaFuncSetAttribute(attn_r_mma,  cudaFuncAttributeMaxDynamicSharedMemorySize, SMEM_DYN);
    cudaFuncSetAttribute(attn_y_mma,  cudaFuncAttributeMaxDynamicSharedMemorySize, SMEM_DYN);

    // bf16 splits of inputs
    {
        int n = MTOT*DIMIN;
        split_bf16<<<(n/4+255)/256, 256>>>(img, Ih, Il, n);
        n = WSZ_TRANS;
        split_bf16<<<(n/4+255)/256, 256>>>(trans_w, Wh+WOFF_TRANS, Wl+WOFF_TRANS, n);
        n = WSZ_LCC;
        split_bf16<<<(n/4+255)/256, 256>>>(gw, Wh+WOFF_G, Wl+WOFF_G, n);
        split_bf16<<<(n/4+255)/256, 256>>>(tw, Wh+WOFF_T, Wl+WOFF_T, n);
        split_bf16<<<(n/4+255)/256, 256>>>(pw, Wh+WOFF_P, Wl+WOFF_P, n);
        split_bf16<<<(n/4+255)/256, 256>>>(ww, Wh+WOFF_W, Wl+WOFF_W, n);
    }

    dim3 gmm(CH/128, MTOT/128);   // (4, 200)

    // encoder: X = img @ trans_w^T + b (fp32 + split)
    mma_gemm<1><<<gmm, 256, SMEM_DYN>>>(Ih, Il, Wh+WOFF_TRANS, Wl+WOFF_TRANS, DIMIN,
        X, Xh, Xl, trans_b, nullptr, nullptr, nullptr, nullptr, nullptr);

    for (int l = 0; l < LAYERS; l++){
        size_t wo = (size_t)l*CH*CH;
        mma_gemm<4><<<gmm, 256, SMEM_DYN>>>(Xh, Xl, Wh+WOFF_G+wo, Wl+WOFF_G+wo, CH,
            nullptr, Gh, Gl, gb + l*CH, nullptr, nullptr, nullptr, nullptr, nullptr);
        mma_gemm<4><<<gmm, 256, SMEM_DYN>>>(Xh, Xl, Wh+WOFF_T+wo, Wl+WOFF_T+wo, CH,
            nullptr, THh, THl, tb + l*CH, nullptr, nullptr, nullptr, nullptr, nullptr);
        mma_gemm<4><<<gmm, 256, SMEM_DYN>>>(Xh, Xl, Wh+WOFF_P+wo, Wl+WOFF_P+wo, CH,
            nullptr, PHh, PHl, pb + l*CH, nullptr, nullptr, nullptr, nullptr, nullptr);

        attn_r_mma<<<BATCH, 256, SMEM_DYN>>>();
        attn_y_mma<<<dim3(CH/128, BATCH), 256, SMEM_DYN>>>();

        if (l == LAYERS-1){
            mma_gemm<3><<<gmm, 256, SMEM_DYN>>>(Yh, Yl, Wh+WOFF_W+wo, Wl+WOFF_W+wo, CH,
                out, nullptr, nullptr, wb + l*CH, X,
                bn_gamma + l*CH, bn_beta + l*CH, bn_mean + l*CH, bn_var + l*CH);
        } else {
            mma_gemm<2><<<gmm, 256, SMEM_DYN>>>(Yh, Yl, Wh+WOFF_W+wo, Wl+WOFF_W+wo, CH,
                X, Xh, Xl, wb + l*CH, X,
                bn_gamma + l*CH, bn_beta + l*CH, bn_mean + l*CH, bn_var + l*CH);
        }
    }
}

// round 6
// speedup vs baseline: 2.9809x; 1.3055x over previous
#include <cuda_runtime.h>
#include <cuda_bf16.h>
#include <cstdint>

#define BATCH  256
#define SEQ    100
#define CH     512
#define NQKV   1536
#define MTOT   (BATCH*SEQ)
#define MPAD   (MTOT+28)
#define DIMIN  2048
#define LAYERS 6
typedef __nv_bfloat16 bf16;

// ---------------- scratch (zero-initialized device globals) ----------------
__device__ float g_X [MTOT*CH];
__device__ bf16  g_Xh[MTOT*CH], g_Xl[MTOT*CH];
__device__ bf16  g_Yh[MTOT*CH], g_Yl[MTOT*CH];
__device__ bf16  g_Ih[MTOT*DIMIN], g_Il[MTOT*DIMIN];
__device__ bf16  g_QKVh[MPAD*NQKV], g_QKVl[MPAD*NQKV];
__device__ bf16  g_Rh[BATCH*128*128], g_Rl[BATCH*128*128];
__device__ float g_bqkv[LAYERS*NQKV];

#define WOFF_TRANS 0
#define WSZ_TRANS  (CH*DIMIN)
#define WOFF_QKV   (WOFF_TRANS + WSZ_TRANS)
#define WSZ_QKV    (LAYERS*3*CH*CH)
#define WOFF_W     (WOFF_QKV + WSZ_QKV)
#define WSZ_W      (LAYERS*CH*CH)
#define WTOT       (WOFF_W + WSZ_W)
__device__ bf16 g_Wh[WTOT], g_Wl[WTOT];

// ---------------- helpers ----------------
__device__ __forceinline__ uint32_t smem_u32(const void* p){
    uint32_t a;
    asm("{ .reg .u64 t; cvta.to.shared.u64 t, %1; cvt.u32.u64 %0, t; }" : "=r"(a) : "l"(p));
    return a;
}
__device__ __forceinline__ void ldsm4(uint32_t &r0, uint32_t &r1, uint32_t &r2, uint32_t &r3, uint32_t a){
    asm volatile("ldmatrix.sync.aligned.m8n8.x4.shared.b16 {%0,%1,%2,%3}, [%4];"
        : "=r"(r0), "=r"(r1), "=r"(r2), "=r"(r3) : "r"(a));
}
__device__ __forceinline__ void ldsm4t(uint32_t &r0, uint32_t &r1, uint32_t &r2, uint32_t &r3, uint32_t a){
    asm volatile("ldmatrix.sync.aligned.m8n8.x4.trans.shared.b16 {%0,%1,%2,%3}, [%4];"
        : "=r"(r0), "=r"(r1), "=r"(r2), "=r"(r3) : "r"(a));
}
__device__ __forceinline__ void mma16816(float* c, const uint32_t* a, const uint32_t* b){
    asm volatile("mma.sync.aligned.m16n8k16.row.col.f32.bf16.bf16.f32 "
        "{%0,%1,%2,%3}, {%4,%5,%6,%7}, {%8,%9}, {%0,%1,%2,%3};"
        : "+f"(c[0]), "+f"(c[1]), "+f"(c[2]), "+f"(c[3])
        : "r"(a[0]), "r"(a[1]), "r"(a[2]), "r"(a[3]), "r"(b[0]), "r"(b[1]));
}
#define CP16(dst, src) asm volatile("cp.async.cg.shared.global [%0], [%1], 16;" :: "r"(dst), "l"(src))
#define CPCOMMIT()     asm volatile("cp.async.commit_group;" ::: "memory")
#define CPWAIT(n)      asm volatile("cp.async.wait_group %0;" :: "n"(n) : "memory")

__device__ __forceinline__ void split1(float v, bf16 &h, bf16 &l){
    h = __float2bfloat16(v);
    l = __float2bfloat16(v - __bfloat162float(h));
}

#define STAGES 3
#define STG_B  32768
#define SMEM_DYN (STAGES*STG_B)

// ---------------- bf16x3 mma GEMM (TN; A,B K-major pitch K) ----------------
// MODE 1: out fp32 = acc+bias, + split | MODE 2: BN+resid fp32, + split
// MODE 3: BN+resid fp32 only          | MODE 4: acc+bias, split only
template<int MODE>
__global__ __launch_bounds__(256, 2)
void mma_gemm(const bf16* __restrict__ Ah, const bf16* __restrict__ Al,
              const bf16* __restrict__ Bh, const bf16* __restrict__ Bl,
              int K, int ldc, float* out, bf16* outh, bf16* outl,
              const float* __restrict__ bias, const float* resid,
              const float* __restrict__ gamma, const float* __restrict__ beta,
              const float* __restrict__ mean,  const float* __restrict__ var)
{
    extern __shared__ __align__(1024) char smem[];
    uint32_t sb = smem_u32(smem);
    int tid = threadIdx.x, wid = tid >> 5, lane = tid & 31;
    int n0 = blockIdx.x * 128, m0 = blockIdx.y * 128;
    Ah += (size_t)m0 * K;  Al += (size_t)m0 * K;
    Bh += (size_t)n0 * K;  Bl += (size_t)n0 * K;

    float acc[2][8][4];
    #pragma unroll
    for (int i = 0; i < 2; i++)
        #pragma unroll
        for (int j = 0; j < 8; j++)
            #pragma unroll
            for (int q = 0; q < 4; q++) acc[i][j][q] = 0.f;

    auto stage_load = [&](int slot, int k0){
        uint32_t base = sb + slot * STG_B;
        #pragma unroll
        for (int i = 0; i < 8; i++){
            int chunk = tid + i * 256;
            int tile = chunk >> 10;
            int cid = chunk & 1023;
            int row = cid >> 3, ch = cid & 7;
            const bf16* hi = tile ? Bh : Ah;
            const bf16* lo = tile ? Bl : Al;
            const bf16* src = (ch < 4 ? hi : lo) + (size_t)row * K + k0 + (ch & 3) * 8;
            uint32_t dst = base + tile * 16384 + row * 128 + ((ch ^ (row & 7)) << 4);
            CP16(dst, src);
        }
    };

    const int kiters = K / 32;
    #pragma unroll
    for (int s = 0; s < STAGES - 1; s++){ stage_load(s, s * 32); CPCOMMIT(); }

    int wm = wid >> 1, wn = wid & 1;
    int g = lane >> 3, r = lane & 7;

    for (int it = 0; it < kiters; it++){
        CPWAIT(STAGES - 2);
        __syncthreads();
        uint32_t sA = sb + (it % STAGES) * STG_B;
        uint32_t sB = sA + 16384;
        #pragma unroll
        for (int kt = 0; kt < 2; kt++){
            uint32_t ah[2][4], al[2][4];
            #pragma unroll
            for (int mt = 0; mt < 2; mt++){
                int row = wm*32 + mt*16 + (g & 1)*8 + r;
                int sw = row & 7;
                uint32_t ra = sA + row * 128;
                int ch = kt*2 + (g >> 1);
                ldsm4(ah[mt][0], ah[mt][1], ah[mt][2], ah[mt][3], ra + ((ch ^ sw) << 4));
                ldsm4(al[mt][0], al[mt][1], al[mt][2], al[mt][3], ra + (((ch+4) ^ sw) << 4));
            }
            #pragma unroll
            for (int np = 0; np < 4; np++){
                int row = wn*64 + np*16 + (g & 1)*8 + r;
                int sw = row & 7;
                uint32_t rb = sB + row * 128;
                int ch = kt*2 + (g >> 1);
                uint32_t t0, t1, t2, t3;
                ldsm4(t0, t1, t2, t3, rb + ((ch ^ sw) << 4));
                {
                    uint32_t b0[2] = {t0, t2}, b1[2] = {t1, t3};
                    #pragma unroll
                    for (int mt = 0; mt < 2; mt++){
                        mma16816(acc[mt][2*np],   ah[mt], b0);
                        mma16816(acc[mt][2*np+1], ah[mt], b1);
                        mma16816(acc[mt][2*np],   al[mt], b0);
                        mma16816(acc[mt][2*np+1], al[mt], b1);
                    }
                }
                ldsm4(t0, t1, t2, t3, rb + (((ch+4) ^ sw) << 4));
                {
                    uint32_t b0[2] = {t0, t2}, b1[2] = {t1, t3};
                    #pragma unroll
                    for (int mt = 0; mt < 2; mt++){
                        mma16816(acc[mt][2*np],   ah[mt], b0);
                        mma16816(acc[mt][2*np+1], ah[mt], b1);
                    }
                }
            }
        }
        if (it + STAGES - 1 < kiters)
            stage_load((it + STAGES - 1) % STAGES, (it + STAGES - 1) * 32);
        CPCOMMIT();
    }

    CPWAIT(0);
    __syncthreads();
    float* cs = (float*)smem;
    float* cf = cs + 128;
    if (tid < 128){
        int c = n0 + tid;
        if (MODE == 2 || MODE == 3){
            float iv = gamma[c] * rsqrtf(var[c] + 1e-5f);
            cs[tid] = iv;
            cf[tid] = (bias[c] - mean[c]) * iv + beta[c];
        } else { cs[tid] = 1.0f; cf[tid] = bias[c]; }
    }
    __syncthreads();

    int q = lane >> 2, p = lane & 3;
    #pragma unroll
    for (int mt = 0; mt < 2; mt++)
        #pragma unroll
        for (int nt = 0; nt < 8; nt++){
            int c = wn*64 + nt*8 + 2*p;
            int gcol = n0 + c;
            #pragma unroll
            for (int h = 0; h < 2; h++){
                int row = m0 + wm*32 + mt*16 + q + h*8;
                float v0 = acc[mt][nt][2*h+0] * cs[c]   + cf[c];
                float v1 = acc[mt][nt][2*h+1] * cs[c+1] + cf[c+1];
                size_t off = (size_t)row * ldc + gcol;
                if (MODE == 2 || MODE == 3){
                    float2 rv = *(const float2*)(resid + off);
                    v0 += rv.x; v1 += rv.y;
                }
                if (MODE != 4)
                    *(float2*)(out + off) = make_float2(v0, v1);
                if (MODE == 1 || MODE == 2 || MODE == 4){
                    bf16 h0, l0, h1, l1;
                    split1(v0, h0, l0); split1(v1, h1, l1);
                    *(__nv_bfloat162*)(outh + off) = __nv_bfloat162(h0, h1);
                    *(__nv_bfloat162*)(outl + off) = __nv_bfloat162(l0, l1);
                }
            }
        }
}

// ---------------- attn_r: R[b] = TH[b]·PH[b]^T / SEQ ----------------------
// TH = QKV cols [512,1024), PH = QKV cols [1024,1536); pitch NQKV.
__global__ __launch_bounds__(256, 2)
void attn_r_mma()
{
    extern __shared__ __align__(1024) char smem[];
    uint32_t sb = smem_u32(smem);
    int tid = threadIdx.x, wid = tid >> 5, lane = tid & 31;
    int b = blockIdx.x;
    const bf16* Ah = g_QKVh + (size_t)b*SEQ*NQKV + 512;
    const bf16* Al = g_QKVl + (size_t)b*SEQ*NQKV + 512;
    const bf16* Bh = g_QKVh + (size_t)b*SEQ*NQKV + 1024;
    const bf16* Bl = g_QKVl + (size_t)b*SEQ*NQKV + 1024;

    float acc[2][8][4];
    #pragma unroll
    for (int i = 0; i < 2; i++)
        #pragma unroll
        for (int j = 0; j < 8; j++)
            #pragma unroll
            for (int q = 0; q < 4; q++) acc[i][j][q] = 0.f;

    auto stage_load = [&](int slot, int k0){
        uint32_t base = sb + slot * STG_B;
        #pragma unroll
        for (int i = 0; i < 8; i++){
            int chunk = tid + i * 256;
            int tile = chunk >> 10;
            int cid = chunk & 1023;
            int row = cid >> 3, ch = cid & 7;
            const bf16* hi = tile ? Bh : Ah;
            const bf16* lo = tile ? Bl : Al;
            const bf16* src = (ch < 4 ? hi : lo) + (size_t)row * NQKV + k0 + (ch & 3) * 8;
            uint32_t dst = base + tile * 16384 + row * 128 + ((ch ^ (row & 7)) << 4);
            CP16(dst, src);
        }
    };

    const int kiters = CH / 32;
    #pragma unroll
    for (int s = 0; s < STAGES - 1; s++){ stage_load(s, s * 32); CPCOMMIT(); }

    int wm = wid >> 1, wn = wid & 1;
    int g = lane >> 3, r = lane & 7;

    for (int it = 0; it < kiters; it++){
        CPWAIT(STAGES - 2);
        __syncthreads();
        uint32_t sA = sb + (it % STAGES) * STG_B;
        uint32_t sB = sA + 16384;
        #pragma unroll
        for (int kt = 0; kt < 2; kt++){
            uint32_t ah[2][4], al[2][4];
            #pragma unroll
            for (int mt = 0; mt < 2; mt++){
                int row = wm*32 + mt*16 + (g & 1)*8 + r;
                int sw = row & 7;
                uint32_t ra = sA + row * 128;
                int ch = kt*2 + (g >> 1);
                ldsm4(ah[mt][0], ah[mt][1], ah[mt][2], ah[mt][3], ra + ((ch ^ sw) << 4));
                ldsm4(al[mt][0], al[mt][1], al[mt][2], al[mt][3], ra + (((ch+4) ^ sw) << 4));
            }
            #pragma unroll
            for (int np = 0; np < 4; np++){
                int row = wn*64 + np*16 + (g & 1)*8 + r;
                int sw = row & 7;
                uint32_t rb = sB + row * 128;
                int ch = kt*2 + (g >> 1);
                uint32_t t0, t1, t2, t3;
                ldsm4(t0, t1, t2, t3, rb + ((ch ^ sw) << 4));
                {
                    uint32_t b0[2] = {t0, t2}, b1[2] = {t1, t3};
                    #pragma unroll
                    for (int mt = 0; mt < 2; mt++){
                        mma16816(acc[mt][2*np],   ah[mt], b0);
                        mma16816(acc[mt][2*np+1], ah[mt], b1);
                        mma16816(acc[mt][2*np],   al[mt], b0);
                        mma16816(acc[mt][2*np+1], al[mt], b1);
                    }
                }
                ldsm4(t0, t1, t2, t3, rb + (((ch+4) ^ sw) << 4));
                {
                    uint32_t b0[2] = {t0, t2}, b1[2] = {t1, t3};
                    #pragma unroll
                    for (int mt = 0; mt < 2; mt++){
                        mma16816(acc[mt][2*np],   ah[mt], b0);
                        mma16816(acc[mt][2*np+1], ah[mt], b1);
                    }
                }
            }
        }
        if (it + STAGES - 1 < kiters)
            stage_load((it + STAGES - 1) % STAGES, (it + STAGES - 1) * 32);
        CPCOMMIT();
    }
    CPWAIT(0);

    const float inv_n = 1.0f / (float)SEQ;
    int q = lane >> 2, p = lane & 3;
    bf16* Rh = g_Rh + (size_t)b * 16384;
    bf16* Rl = g_Rl + (size_t)b * 16384;
    #pragma unroll
    for (int mt = 0; mt < 2; mt++)
        #pragma unroll
        for (int nt = 0; nt < 8; nt++){
            int c = wn*64 + nt*8 + 2*p;
            #pragma unroll
            for (int h = 0; h < 2; h++){
                int row = wm*32 + mt*16 + q + h*8;
                bool okr = row < SEQ;
                float v0 = (okr && c   < SEQ) ? acc[mt][nt][2*h+0] * inv_n : 0.f;
                float v1 = (okr && c+1 < SEQ) ? acc[mt][nt][2*h+1] * inv_n : 0.f;
                bf16 h0, l0, h1, l1;
                split1(v0, h0, l0); split1(v1, h1, l1);
                size_t off = (size_t)row * 128 + c;
                *(__nv_bfloat162*)(Rh + off) = __nv_bfloat162(h0, h1);
                *(__nv_bfloat162*)(Rl + off) = __nv_bfloat162(l0, l1);
            }
        }
}

// ---------------- attn_y: Y[b] = R[b]·G[b]  (G = QKV cols [0,512)) --------
__global__ __launch_bounds__(256, 2)
void attn_y_mma()
{
    extern __shared__ __align__(1024) char smem[];
    uint32_t sb = smem_u32(smem);
    int tid = threadIdx.x, wid = tid >> 5, lane = tid & 31;
    int b = blockIdx.y, n0 = blockIdx.x * 128;

    float acc[2][8][4];
    #pragma unroll
    for (int i = 0; i < 2; i++)
        #pragma unroll
        for (int j = 0; j < 8; j++)
            #pragma unroll
            for (int q = 0; q < 4; q++) acc[i][j][q] = 0.f;

    auto stage_load = [&](int slot, int k0){
        uint32_t base = sb + slot * STG_B;
        #pragma unroll
        for (int i = 0; i < 4; i++){
            int cid = tid + i * 256;
            int row = cid >> 3, ch = cid & 7;
            const bf16* src = (ch < 4 ? g_Rh : g_Rl)
                + (size_t)b * 16384 + row * 128 + k0 + (ch & 3) * 8;
            uint32_t dst = base + row * 128 + ((ch ^ (row & 7)) << 4);
            CP16(dst, src);
        }
        #pragma unroll
        for (int i = 0; i < 4; i++){
            int cid = tid + i * 256;
            int buf = cid >> 9, rem = cid & 511;
            int k = rem >> 4, c = rem & 15;
            const bf16* src = (buf ? g_QKVl : g_QKVh)
                + (size_t)(b * SEQ + k0 + k) * NQKV + n0 + c * 8;
            uint32_t dst = base + 16384 + buf * 8192 + k * 256 + ((c ^ (k & 7)) << 4);
            CP16(dst, src);
        }
    };

    const int kiters = 4;
    #pragma unroll
    for (int s = 0; s < STAGES - 1; s++){ stage_load(s, s * 32); CPCOMMIT(); }

    int wm = wid >> 1, wn = wid & 1;
    int g = lane >> 3, r = lane & 7;
    int m = lane >> 3;

    for (int it = 0; it < kiters; it++){
        CPWAIT(STAGES - 2);
        __syncthreads();
        uint32_t sA = sb + (it % STAGES) * STG_B;
        uint32_t sG = sA + 16384;
        #pragma unroll
        for (int kt = 0; kt < 2; kt++){
            uint32_t ah[2][4], al[2][4];
            #pragma unroll
            for (int mt = 0; mt < 2; mt++){
                int row = wm*32 + mt*16 + (g & 1)*8 + r;
                int sw = row & 7;
                uint32_t ra = sA + row * 128;
                int ch = kt*2 + (g >> 1);
                ldsm4(ah[mt][0], ah[mt][1], ah[mt][2], ah[mt][3], ra + ((ch ^ sw) << 4));
                ldsm4(al[mt][0], al[mt][1], al[mt][2], al[mt][3], ra + (((ch+4) ^ sw) << 4));
            }
            int krow = kt*16 + (lane & 7) + (m & 1)*8;
            int ksw = krow & 7;
            #pragma unroll
            for (int np = 0; np < 4; np++){
                int cb = wn*8 + np*2 + (m >> 1);
                uint32_t t0, t1, t2, t3;
                ldsm4t(t0, t1, t2, t3, sG + krow*256 + ((cb ^ ksw) << 4));
                {
                    uint32_t b0[2] = {t0, t1}, b1[2] = {t2, t3};
                    #pragma unroll
                    for (int mt = 0; mt < 2; mt++){
                        mma16816(acc[mt][2*np],   ah[mt], b0);
                        mma16816(acc[mt][2*np+1], ah[mt], b1);
                        mma16816(acc[mt][2*np],   al[mt], b0);
                        mma16816(acc[mt][2*np+1], al[mt], b1);
                    }
                }
                ldsm4t(t0, t1, t2, t3, sG + 8192 + krow*256 + ((cb ^ ksw) << 4));
                {
                    uint32_t b0[2] = {t0, t1}, b1[2] = {t2, t3};
                    #pragma unroll
                    for (int mt = 0; mt < 2; mt++){
                        mma16816(acc[mt][2*np],   ah[mt], b0);
                        mma16816(acc[mt][2*np+1], ah[mt], b1);
                    }
                }
            }
        }
        if (it + STAGES - 1 < kiters)
            stage_load((it + STAGES - 1) % STAGES, (it + STAGES - 1) * 32);
        CPCOMMIT();
    }
    CPWAIT(0);

    int q = lane >> 2, p = lane & 3;
    #pragma unroll
    for (int mt = 0; mt < 2; mt++)
        #pragma unroll
        for (int nt = 0; nt < 8; nt++){
            int c = wn*64 + nt*8 + 2*p;
            #pragma unroll
            for (int h = 0; h < 2; h++){
                int row = wm*32 + mt*16 + q + h*8;
                if (row < SEQ){
                    float v0 = acc[mt][nt][2*h+0];
                    float v1 = acc[mt][nt][2*h+1];
                    bf16 h0, l0, h1, l1;
                    split1(v0, h0, l0); split1(v1, h1, l1);
                    size_t off = (size_t)(b*SEQ + row) * CH + n0 + c;
                    *(__nv_bfloat162*)(g_Yh + off) = __nv_bfloat162(h0, h1);
                    *(__nv_bfloat162*)(g_Yl + off) = __nv_bfloat162(l0, l1);
                }
            }
        }
}

// ---------------- splits ----------------
__global__ void split_bf16(const float* __restrict__ in, bf16* __restrict__ hi,
                           bf16* __restrict__ lo, int n)
{
    int i = (blockIdx.x * blockDim.x + threadIdx.x) * 4;
    if (i < n){
        float4 x = *(const float4*)(in + i);
        bf16 h0,l0,h1,l1,h2,l2,h3,l3;
        split1(x.x,h0,l0); split1(x.y,h1,l1); split1(x.z,h2,l2); split1(x.w,h3,l3);
        *(__nv_bfloat162*)(hi + i)     = __nv_bfloat162(h0, h1);
        *(__nv_bfloat162*)(hi + i + 2) = __nv_bfloat162(h2, h3);
        *(__nv_bfloat162*)(lo + i)     = __nv_bfloat162(l0, l1);
        *(__nv_bfloat162*)(lo + i + 2) = __nv_bfloat162(l2, l3);
    }
}

// g/t/p weights -> per-layer-interleaved QKV block.  blockIdx.y = which.
__global__ void split_qkv(const float* __restrict__ gw, const float* __restrict__ tw,
                          const float* __restrict__ pw)
{
    int which = blockIdx.y;
    const float* src = which == 0 ? gw : which == 1 ? tw : pw;
    int i = (blockIdx.x * blockDim.x + threadIdx.x) * 4;
    if (i < LAYERS*CH*CH){
        int l = i / (CH*CH);
        int w = i - l * (CH*CH);
        size_t d = (size_t)WOFF_QKV + (size_t)l * 3*CH*CH + (size_t)which * CH*CH + w;
        float4 x = *(const float4*)(src + i);
        bf16 h0,l0,h1,l1,h2,l2,h3,l3;
        split1(x.x,h0,l0); split1(x.y,h1,l1); split1(x.z,h2,l2); split1(x.w,h3,l3);
        *(__nv_bfloat162*)(g_Wh + d)     = __nv_bfloat162(h0, h1);
        *(__nv_bfloat162*)(g_Wh + d + 2) = __nv_bfloat162(h2, h3);
        *(__nv_bfloat162*)(g_Wl + d)     = __nv_bfloat162(l0, l1);
        *(__nv_bfloat162*)(g_Wl + d + 2) = __nv_bfloat162(l2, l3);
    }
}

__global__ void bias_fuse(const float* __restrict__ gb, const float* __restrict__ tb,
                          const float* __restrict__ pb)
{
    int i = blockIdx.x * blockDim.x + threadIdx.x;
    if (i < LAYERS*NQKV){
        int l = i / NQKV, c = i % NQKV;
        float v = c < 512 ? gb[l*512 + c] : c < 1024 ? tb[l*512 + c - 512] : pb[l*512 + c - 1024];
        g_bqkv[i] = v;
    }
}

// ---------------- host ----------------
extern "C" void kernel_launch(void* const* d_in, const int* in_sizes, int n_in,
                              void* d_out, int out_size)
{
    (void)in_sizes; (void)n_in; (void)out_size;
    const float* img     = (const float*)d_in[0];
    const float* trans_w = (const float*)d_in[1];
    const float* trans_b = (const float*)d_in[2];
    const float* gw = (const float*)d_in[3];
    const float* gb = (const float*)d_in[4];
    const float* tw = (const float*)d_in[5];
    const float* tb = (const float*)d_in[6];
    const float* pw = (const float*)d_in[7];
    const float* pb = (const float*)d_in[8];
    const float* ww = (const float*)d_in[9];
    const float* wb = (const float*)d_in[10];
    const float* bn_gamma = (const float*)d_in[11];
    const float* bn_beta  = (const float*)d_in[12];
    const float* bn_mean  = (const float*)d_in[13];
    const float* bn_var   = (const float*)d_in[14];
    float* out = (float*)d_out;

    float *X, *bqkv;
    bf16 *Xh, *Xl, *Yh, *Yl, *Ih, *Il, *Wh, *Wl, *Qh, *Ql;
    cudaGetSymbolAddress((void**)&X,   g_X);
    cudaGetSymbolAddress((void**)&Xh,  g_Xh);
    cudaGetSymbolAddress((void**)&Xl,  g_Xl);
    cudaGetSymbolAddress((void**)&Yh,  g_Yh);
    cudaGetSymbolAddress((void**)&Yl,  g_Yl);
    cudaGetSymbolAddress((void**)&Ih,  g_Ih);
    cudaGetSymbolAddress((void**)&Il,  g_Il);
    cudaGetSymbolAddress((void**)&Wh,  g_Wh);
    cudaGetSymbolAddress((void**)&Wl,  g_Wl);
    cudaGetSymbolAddress((void**)&Qh,  g_QKVh);
    cudaGetSymbolAddress((void**)&Ql,  g_QKVl);
    cudaGetSymbolAddress((void**)&bqkv, g_bqkv);

    cudaFuncSetAttribute(mma_gemm<1>, cudaFuncAttributeMaxDynamicSharedMemorySize, SMEM_DYN);
    cudaFuncSetAttribute(mma_gemm<2>, cudaFuncAttributeMaxDynamicSharedMemorySize, SMEM_DYN);
    cudaFuncSetAttribute(mma_gemm<3>, cudaFuncAttributeMaxDynamicSharedMemorySize, SMEM_DYN);
    cudaFuncSetAttribute(mma_gemm<4>, cudaFuncAttributeMaxDynamicSharedMemorySize, SMEM_DYN);
    cudaFuncSetAttribute(attn_r_mma,  cudaFuncAttributeMaxDynamicSharedMemorySize, SMEM_DYN);
    cudaFuncSetAttribute(attn_y_mma,  cudaFuncAttributeMaxDynamicSharedMemorySize, SMEM_DYN);

    // 0: fused bias, 1: img split, 2: trans split, 3: qkv split, 4: w split
    bias_fuse<<<(LAYERS*NQKV + 255)/256, 256>>>(gb, tb, pb);
    {
        int n = MTOT*DIMIN;
        split_bf16<<<(n/4+255)/256, 256>>>(img, Ih, Il, n);
        n = WSZ_TRANS;
        split_bf16<<<(n/4+255)/256, 256>>>(trans_w, Wh+WOFF_TRANS, Wl+WOFF_TRANS, n);
        split_qkv<<<dim3((LAYERS*CH*CH/4+255)/256, 3), 256>>>(gw, tw, pw);
        n = LAYERS*CH*CH;
        split_bf16<<<(n/4+255)/256, 256>>>(ww, Wh+WOFF_W, Wl+WOFF_W, n);
    }

    dim3 gmm(CH/128, MTOT/128);     // (4, 200)
    dim3 gqkv(NQKV/128, MTOT/128);  // (12, 200)

    // 5: encoder (ncu -s 5 profiles this)
    mma_gemm<1><<<gmm, 256, SMEM_DYN>>>(Ih, Il, Wh+WOFF_TRANS, Wl+WOFF_TRANS, DIMIN, CH,
        X, Xh, Xl, trans_b, nullptr, nullptr, nullptr, nullptr, nullptr);

    for (int l = 0; l < LAYERS; l++){
        size_t qo = (size_t)l * 3*CH*CH;
        size_t wo = (size_t)l * CH*CH;

        mma_gemm<4><<<gqkv, 256, SMEM_DYN>>>(Xh, Xl, Wh+WOFF_QKV+qo, Wl+WOFF_QKV+qo, CH, NQKV,
            nullptr, Qh, Ql, bqkv + l*NQKV, nullptr, nullptr, nullptr, nullptr, nullptr);

        attn_r_mma<<<BATCH, 256, SMEM_DYN>>>();
        attn_y_mma<<<dim3(CH/128, BATCH), 256, SMEM_DYN>>>();

        if (l == LAYERS-1){
            mma_gemm<3><<<gmm, 256, SMEM_DYN>>>(Yh, Yl, Wh+WOFF_W+wo, Wl+WOFF_W+wo, CH, CH,
                out, nullptr, nullptr, wb + l*CH, X,
                bn_gamma + l*CH, bn_beta + l*CH, bn_mean + l*CH, bn_var + l*CH);
        } else {
            mma_gemm<2><<<gmm, 256, SMEM_DYN>>>(Yh, Yl, Wh+WOFF_W+wo, Wl+WOFF_W+wo, CH, CH,
                X, Xh, Xl, wb + l*CH, X,
                bn_gamma + l*CH, bn_beta + l*CH, bn_mean + l*CH, bn_var + l*CH);
        }
    }
}

// round 8
// speedup vs baseline: 3.5186x; 1.1804x over previous
#include <cuda_runtime.h>
#include <cuda_bf16.h>
#include <cstdint>

#define BATCH  256
#define SEQ    100
#define CH     512
#define NQKV   1536
#define MTOT   (BATCH*SEQ)
#define MPAD   (MTOT+28)
#define DIMIN  2048
#define LAYERS 6
typedef __nv_bfloat16 bf16;

// ---------------- scratch (zero-initialized device globals) ----------------
__device__ float g_X [MTOT*CH];
__device__ bf16  g_Xh[MTOT*CH], g_Xl[MTOT*CH];
__device__ bf16  g_Ih[MTOT*DIMIN], g_Il[MTOT*DIMIN];
__device__ bf16  g_QKVh[MPAD*NQKV], g_QKVl[MPAD*NQKV];
__device__ bf16  g_Rh[BATCH*128*128], g_Rl[BATCH*128*128];
__device__ float g_bqkv[LAYERS*NQKV];
__device__ float g_S[BATCH*128];
__device__ float g_wgb[LAYERS*CH];
__device__ bf16  g_Vh[LAYERS*CH*CH],  g_Vl[LAYERS*CH*CH];
__device__ bf16  g_GWh[LAYERS*CH*CH], g_GWl[LAYERS*CH*CH];

#define WOFF_TRANS 0
#define WSZ_TRANS  (CH*DIMIN)
#define WOFF_TP    (WOFF_TRANS + WSZ_TRANS)
#define WSZ_TP     (LAYERS*2*CH*CH)
#define WOFF_W     (WOFF_TP + WSZ_TP)
#define WTOT       (WOFF_W + LAYERS*CH*CH)
__device__ bf16 g_Wh[WTOT], g_Wl[WTOT];

// ---------------- helpers ----------------
__device__ __forceinline__ uint32_t smem_u32(const void* p){
    uint32_t a;
    asm("{ .reg .u64 t; cvta.to.shared.u64 t, %1; cvt.u32.u64 %0, t; }" : "=r"(a) : "l"(p));
    return a;
}
__device__ __forceinline__ void ldsm4(uint32_t &r0, uint32_t &r1, uint32_t &r2, uint32_t &r3, uint32_t a){
    asm volatile("ldmatrix.sync.aligned.m8n8.x4.shared.b16 {%0,%1,%2,%3}, [%4];"
        : "=r"(r0), "=r"(r1), "=r"(r2), "=r"(r3) : "r"(a));
}
__device__ __forceinline__ void ldsm4t(uint32_t &r0, uint32_t &r1, uint32_t &r2, uint32_t &r3, uint32_t a){
    asm volatile("ldmatrix.sync.aligned.m8n8.x4.trans.shared.b16 {%0,%1,%2,%3}, [%4];"
        : "=r"(r0), "=r"(r1), "=r"(r2), "=r"(r3) : "r"(a));
}
__device__ __forceinline__ void mma16816(float* c, const uint32_t* a, const uint32_t* b){
    asm volatile("mma.sync.aligned.m16n8k16.row.col.f32.bf16.bf16.f32 "
        "{%0,%1,%2,%3}, {%4,%5,%6,%7}, {%8,%9}, {%0,%1,%2,%3};"
        : "+f"(c[0]), "+f"(c[1]), "+f"(c[2]), "+f"(c[3])
        : "r"(a[0]), "r"(a[1]), "r"(a[2]), "r"(a[3]), "r"(b[0]), "r"(b[1]));
}
#define CP16(dst, src) asm volatile("cp.async.cg.shared.global [%0], [%1], 16;" :: "r"(dst), "l"(src))
#define CPCOMMIT()     asm volatile("cp.async.commit_group;" ::: "memory")
#define CPWAIT(n)      asm volatile("cp.async.wait_group %0;" :: "n"(n) : "memory")

__device__ __forceinline__ void split1(float v, bf16 &h, bf16 &l){
    h = __float2bfloat16(v);
    l = __float2bfloat16(v - __bfloat162float(h));
}

#define STAGES 3
#define STG_B  32768
#define SMEM_DYN (STAGES*STG_B)

// Shared mainloop fragment macro (TN: A, B both K-major in smem)
#define TN_MAINLOOP_BODY(sA, sB) \
    { \
        _Pragma("unroll") \
        for (int kt = 0; kt < 2; kt++){ \
            uint32_t ah[2][4], al[2][4]; \
            _Pragma("unroll") \
            for (int mt = 0; mt < 2; mt++){ \
                int row = wm*32 + mt*16 + (g & 1)*8 + r; \
                int sw = row & 7; \
                uint32_t ra = (sA) + row * 128; \
                int ch = kt*2 + (g >> 1); \
                ldsm4(ah[mt][0], ah[mt][1], ah[mt][2], ah[mt][3], ra + ((ch ^ sw) << 4)); \
                ldsm4(al[mt][0], al[mt][1], al[mt][2], al[mt][3], ra + (((ch+4) ^ sw) << 4)); \
            } \
            _Pragma("unroll") \
            for (int np = 0; np < 4; np++){ \
                int row = wn*64 + np*16 + (g & 1)*8 + r; \
                int sw = row & 7; \
                uint32_t rb = (sB) + row * 128; \
                int ch = kt*2 + (g >> 1); \
                uint32_t t0, t1, t2, t3; \
                ldsm4(t0, t1, t2, t3, rb + ((ch ^ sw) << 4)); \
                { \
                    uint32_t b0[2] = {t0, t2}, b1[2] = {t1, t3}; \
                    _Pragma("unroll") \
                    for (int mt = 0; mt < 2; mt++){ \
                        mma16816(acc[mt][2*np],   ah[mt], b0); \
                        mma16816(acc[mt][2*np+1], ah[mt], b1); \
                        mma16816(acc[mt][2*np],   al[mt], b0); \
                        mma16816(acc[mt][2*np+1], al[mt], b1); \
                    } \
                } \
                ldsm4(t0, t1, t2, t3, rb + (((ch+4) ^ sw) << 4)); \
                { \
                    uint32_t b0[2] = {t0, t2}, b1[2] = {t1, t3}; \
                    _Pragma("unroll") \
                    for (int mt = 0; mt < 2; mt++){ \
                        mma16816(acc[mt][2*np],   ah[mt], b0); \
                        mma16816(acc[mt][2*np+1], ah[mt], b1); \
                    } \
                } \
            } \
        } \
    }

// NN mainloop: A K-major, B row-major (k x n) via ldsm.trans
#define NN_MAINLOOP_BODY(sA, sG) \
    { \
        _Pragma("unroll") \
        for (int kt = 0; kt < 2; kt++){ \
            uint32_t ah[2][4], al[2][4]; \
            _Pragma("unroll") \
            for (int mt = 0; mt < 2; mt++){ \
                int row = wm*32 + mt*16 + (g & 1)*8 + r; \
                int sw = row & 7; \
                uint32_t ra = (sA) + row * 128; \
                int ch = kt*2 + (g >> 1); \
                ldsm4(ah[mt][0], ah[mt][1], ah[mt][2], ah[mt][3], ra + ((ch ^ sw) << 4)); \
                ldsm4(al[mt][0], al[mt][1], al[mt][2], al[mt][3], ra + (((ch+4) ^ sw) << 4)); \
            } \
            int krow = kt*16 + (lane & 7) + (m & 1)*8; \
            int ksw = krow & 7; \
            _Pragma("unroll") \
            for (int np = 0; np < 4; np++){ \
                int cb = wn*8 + np*2 + (m >> 1); \
                uint32_t t0, t1, t2, t3; \
                ldsm4t(t0, t1, t2, t3, (sG) + krow*256 + ((cb ^ ksw) << 4)); \
                { \
                    uint32_t b0[2] = {t0, t1}, b1[2] = {t2, t3}; \
                    _Pragma("unroll") \
                    for (int mt = 0; mt < 2; mt++){ \
                        mma16816(acc[mt][2*np],   ah[mt], b0); \
                        mma16816(acc[mt][2*np+1], ah[mt], b1); \
                        mma16816(acc[mt][2*np],   al[mt], b0); \
                        mma16816(acc[mt][2*np+1], al[mt], b1); \
                    } \
                } \
                ldsm4t(t0, t1, t2, t3, (sG) + 8192 + krow*256 + ((cb ^ ksw) << 4)); \
                { \
                    uint32_t b0[2] = {t0, t1}, b1[2] = {t2, t3}; \
                    _Pragma("unroll") \
                    for (int mt = 0; mt < 2; mt++){ \
                        mma16816(acc[mt][2*np],   ah[mt], b0); \
                        mma16816(acc[mt][2*np+1], ah[mt], b1); \
                    } \
                } \
            } \
        } \
    }

#define ZERO_ACC() \
    float acc[2][8][4]; \
    _Pragma("unroll") \
    for (int i = 0; i < 2; i++) \
        _Pragma("unroll") \
        for (int j = 0; j < 8; j++) \
            _Pragma("unroll") \
            for (int qq = 0; qq < 4; qq++) acc[i][j][qq] = 0.f;

// ---------------- encoder GEMM (TN, fp32 out + split) ----------------------
__global__ __launch_bounds__(256, 2)
void enc_gemm(const bf16* __restrict__ Ah, const bf16* __restrict__ Al,
              const bf16* __restrict__ Bh, const bf16* __restrict__ Bl,
              int K, float* out, bf16* outh, bf16* outl,
              const float* __restrict__ bias)
{
    extern __shared__ __align__(1024) char smem[];
    uint32_t sb = smem_u32(smem);
    int tid = threadIdx.x, wid = tid >> 5, lane = tid & 31;
    int n0 = blockIdx.x * 128, m0 = blockIdx.y * 128;
    Ah += (size_t)m0 * K;  Al += (size_t)m0 * K;
    Bh += (size_t)n0 * K;  Bl += (size_t)n0 * K;
    ZERO_ACC();

    auto stage_load = [&](int slot, int k0){
        uint32_t base = sb + slot * STG_B;
        #pragma unroll
        for (int i = 0; i < 8; i++){
            int chunk = tid + i * 256;
            int tile = chunk >> 10;
            int cid = chunk & 1023;
            int row = cid >> 3, ch = cid & 7;
            const bf16* hi = tile ? Bh : Ah;
            const bf16* lo = tile ? Bl : Al;
            const bf16* src = (ch < 4 ? hi : lo) + (size_t)row * K + k0 + (ch & 3) * 8;
            uint32_t dst = base + tile * 16384 + row * 128 + ((ch ^ (row & 7)) << 4);
            CP16(dst, src);
        }
    };
    const int kiters = K / 32;
    #pragma unroll
    for (int s = 0; s < STAGES - 1; s++){ stage_load(s, s * 32); CPCOMMIT(); }

    int wm = wid >> 1, wn = wid & 1;
    int g = lane >> 3, r = lane & 7;

    for (int it = 0; it < kiters; it++){
        CPWAIT(STAGES - 2);
        __syncthreads();
        uint32_t sA = sb + (it % STAGES) * STG_B;
        TN_MAINLOOP_BODY(sA, sA + 16384);
        if (it + STAGES - 1 < kiters)
            stage_load((it + STAGES - 1) % STAGES, (it + STAGES - 1) * 32);
        CPCOMMIT();
    }

    CPWAIT(0);
    __syncthreads();
    float* cf = (float*)smem;
    if (tid < 128) cf[tid] = bias[n0 + tid];
    __syncthreads();

    int q = lane >> 2, p = lane & 3;
    #pragma unroll
    for (int mt = 0; mt < 2; mt++)
        #pragma unroll
        for (int nt = 0; nt < 8; nt++){
            int c = wn*64 + nt*8 + 2*p;
            #pragma unroll
            for (int h = 0; h < 2; h++){
                int row = m0 + wm*32 + mt*16 + q + h*8;
                float v0 = acc[mt][nt][2*h+0] + cf[c];
                float v1 = acc[mt][nt][2*h+1] + cf[c+1];
                size_t off = (size_t)row * CH + n0 + c;
                *(float2*)(out + off) = make_float2(v0, v1);
                bf16 h0, l0, h1, l1;
                split1(v0, h0, l0); split1(v1, h1, l1);
                *(__nv_bfloat162*)(outh + off) = __nv_bfloat162(h0, h1);
                *(__nv_bfloat162*)(outl + off) = __nv_bfloat162(l0, l1);
            }
        }
}

// ---------------- QKV GEMM (TN, split-only out; B = [V | tw,pw]) -----------
__global__ __launch_bounds__(256, 2)
void qkv_gemm(const bf16* __restrict__ Ah, const bf16* __restrict__ Al,
              const bf16* __restrict__ Vh, const bf16* __restrict__ Vl,
              const bf16* __restrict__ TPh, const bf16* __restrict__ TPl,
              const float* __restrict__ bias)
{
    extern __shared__ __align__(1024) char smem[];
    uint32_t sb = smem_u32(smem);
    int tid = threadIdx.x, wid = tid >> 5, lane = tid & 31;
    int n0 = blockIdx.x * 128, m0 = blockIdx.y * 128;
    const int K = CH;
    Ah += (size_t)m0 * K;  Al += (size_t)m0 * K;
    const bf16 *Bh, *Bl;
    if (n0 < 512){ Bh = Vh + (size_t)n0 * K;        Bl = Vl + (size_t)n0 * K; }
    else         { Bh = TPh + (size_t)(n0-512) * K; Bl = TPl + (size_t)(n0-512) * K; }
    ZERO_ACC();

    auto stage_load = [&](int slot, int k0){
        uint32_t base = sb + slot * STG_B;
        #pragma unroll
        for (int i = 0; i < 8; i++){
            int chunk = tid + i * 256;
            int tile = chunk >> 10;
            int cid = chunk & 1023;
            int row = cid >> 3, ch = cid & 7;
            const bf16* hi = tile ? Bh : Ah;
            const bf16* lo = tile ? Bl : Al;
            const bf16* src = (ch < 4 ? hi : lo) + (size_t)row * K + k0 + (ch & 3) * 8;
            uint32_t dst = base + tile * 16384 + row * 128 + ((ch ^ (row & 7)) << 4);
            CP16(dst, src);
        }
    };
    const int kiters = K / 32;
    #pragma unroll
    for (int s = 0; s < STAGES - 1; s++){ stage_load(s, s * 32); CPCOMMIT(); }

    int wm = wid >> 1, wn = wid & 1;
    int g = lane >> 3, r = lane & 7;

    for (int it = 0; it < kiters; it++){
        CPWAIT(STAGES - 2);
        __syncthreads();
        uint32_t sA = sb + (it % STAGES) * STG_B;
        TN_MAINLOOP_BODY(sA, sA + 16384);
        if (it + STAGES - 1 < kiters)
            stage_load((it + STAGES - 1) % STAGES, (it + STAGES - 1) * 32);
        CPCOMMIT();
    }

    CPWAIT(0);
    __syncthreads();
    float* cf = (float*)smem;
    if (tid < 128) cf[tid] = bias[n0 + tid];
    __syncthreads();

    int q = lane >> 2, p = lane & 3;
    #pragma unroll
    for (int mt = 0; mt < 2; mt++)
        #pragma unroll
        for (int nt = 0; nt < 8; nt++){
            int c = wn*64 + nt*8 + 2*p;
            #pragma unroll
            for (int h = 0; h < 2; h++){
                int row = m0 + wm*32 + mt*16 + q + h*8;
                float v0 = acc[mt][nt][2*h+0] + cf[c];
                float v1 = acc[mt][nt][2*h+1] + cf[c+1];
                size_t off = (size_t)row * NQKV + n0 + c;
                bf16 h0, l0, h1, l1;
                split1(v0, h0, l0); split1(v1, h1, l1);
                *(__nv_bfloat162*)(g_QKVh + off) = __nv_bfloat162(h0, h1);
                *(__nv_bfloat162*)(g_QKVl + off) = __nv_bfloat162(l0, l1);
            }
        }
}

// ---------------- V = ww·gw per layer (NN, split-only out) -----------------
__global__ __launch_bounds__(256, 2)
void vgemm()
{
    extern __shared__ __align__(1024) char smem[];
    uint32_t sb = smem_u32(smem);
    int tid = threadIdx.x, wid = tid >> 5, lane = tid & 31;
    int l = blockIdx.z, n0 = blockIdx.x * 128, m0 = blockIdx.y * 128;
    const bf16* Ah = g_Wh + WOFF_W + (size_t)l*CH*CH + (size_t)m0*CH;
    const bf16* Al = g_Wl + WOFF_W + (size_t)l*CH*CH + (size_t)m0*CH;
    const bf16* Bh = g_GWh + (size_t)l*CH*CH;
    const bf16* Bl = g_GWl + (size_t)l*CH*CH;
    ZERO_ACC();

    auto stage_load = [&](int slot, int k0){
        uint32_t base = sb + slot * STG_B;
        #pragma unroll
        for (int i = 0; i < 4; i++){
            int cid = tid + i * 256;
            int row = cid >> 3, ch = cid & 7;
            const bf16* src = (ch < 4 ? Ah : Al) + (size_t)row * CH + k0 + (ch & 3) * 8;
            uint32_t dst = base + row * 128 + ((ch ^ (row & 7)) << 4);
            CP16(dst, src);
        }
        #pragma unroll
        for (int i = 0; i < 4; i++){
            int cid = tid + i * 256;
            int buf = cid >> 9, rem = cid & 511;
            int k = rem >> 4, c = rem & 15;
            const bf16* src = (buf ? Bl : Bh) + (size_t)(k0 + k) * CH + n0 + c * 8;
            uint32_t dst = base + 16384 + buf * 8192 + k * 256 + ((c ^ (k & 7)) << 4);
            CP16(dst, src);
        }
    };
    const int kiters = CH / 32;
    #pragma unroll
    for (int s = 0; s < STAGES - 1; s++){ stage_load(s, s * 32); CPCOMMIT(); }

    int wm = wid >> 1, wn = wid & 1;
    int g = lane >> 3, r = lane & 7;
    int m = lane >> 3;

    for (int it = 0; it < kiters; it++){
        CPWAIT(STAGES - 2);
        __syncthreads();
        uint32_t sA = sb + (it % STAGES) * STG_B;
        NN_MAINLOOP_BODY(sA, sA + 16384);
        if (it + STAGES - 1 < kiters)
            stage_load((it + STAGES - 1) % STAGES, (it + STAGES - 1) * 32);
        CPCOMMIT();
    }
    CPWAIT(0);

    int q = lane >> 2, p = lane & 3;
    bf16* Vh = g_Vh + (size_t)l*CH*CH;
    bf16* Vl = g_Vl + (size_t)l*CH*CH;
    #pragma unroll
    for (int mt = 0; mt < 2; mt++)
        #pragma unroll
        for (int nt = 0; nt < 8; nt++){
            int c = wn*64 + nt*8 + 2*p;
            #pragma unroll
            for (int h = 0; h < 2; h++){
                int row = m0 + wm*32 + mt*16 + q + h*8;
                float v0 = acc[mt][nt][2*h+0];
                float v1 = acc[mt][nt][2*h+1];
                bf16 h0, l0, h1, l1;
                split1(v0, h0, l0); split1(v1, h1, l1);
                size_t off = (size_t)row * CH + n0 + c;
                *(__nv_bfloat162*)(Vh + off) = __nv_bfloat162(h0, h1);
                *(__nv_bfloat162*)(Vl + off) = __nv_bfloat162(l0, l1);
            }
        }
}

// ---------------- attn_r: R[b] = TH·PH^T / SEQ, + row sums -----------------
__global__ __launch_bounds__(256, 2)
void attn_r_mma()
{
    extern __shared__ __align__(1024) char smem[];
    uint32_t sb = smem_u32(smem);
    int tid = threadIdx.x, wid = tid >> 5, lane = tid & 31;
    int b = blockIdx.x;
    const bf16* Ah = g_QKVh + (size_t)b*SEQ*NQKV + 512;
    const bf16* Al = g_QKVl + (size_t)b*SEQ*NQKV + 512;
    const bf16* Bh = g_QKVh + (size_t)b*SEQ*NQKV + 1024;
    const bf16* Bl = g_QKVl + (size_t)b*SEQ*NQKV + 1024;
    ZERO_ACC();

    auto stage_load = [&](int slot, int k0){
        uint32_t base = sb + slot * STG_B;
        #pragma unroll
        for (int i = 0; i < 8; i++){
            int chunk = tid + i * 256;
            int tile = chunk >> 10;
            int cid = chunk & 1023;
            int row = cid >> 3, ch = cid & 7;
            const bf16* hi = tile ? Bh : Ah;
            const bf16* lo = tile ? Bl : Al;
            const bf16* src = (ch < 4 ? hi : lo) + (size_t)row * NQKV + k0 + (ch & 3) * 8;
            uint32_t dst = base + tile * 16384 + row * 128 + ((ch ^ (row & 7)) << 4);
            CP16(dst, src);
        }
    };
    const int kiters = CH / 32;
    #pragma unroll
    for (int s = 0; s < STAGES - 1; s++){ stage_load(s, s * 32); CPCOMMIT(); }

    int wm = wid >> 1, wn = wid & 1;
    int g = lane >> 3, r = lane & 7;

    for (int it = 0; it < kiters; it++){
        CPWAIT(STAGES - 2);
        __syncthreads();
        uint32_t sA = sb + (it % STAGES) * STG_B;
        TN_MAINLOOP_BODY(sA, sA + 16384);
        if (it + STAGES - 1 < kiters)
            stage_load((it + STAGES - 1) % STAGES, (it + STAGES - 1) * 32);
        CPCOMMIT();
    }
    CPWAIT(0);
    __syncthreads();
    float* s_sm = (float*)smem;
    if (tid < 128) s_sm[tid] = 0.f;
    __syncthreads();

    const float inv_n = 1.0f / (float)SEQ;
    int q = lane >> 2, p = lane & 3;
    bf16* Rh = g_Rh + (size_t)b * 16384;
    bf16* Rl = g_Rl + (size_t)b * 16384;
    float rs[2][2] = {{0.f, 0.f}, {0.f, 0.f}};
    #pragma unroll
    for (int mt = 0; mt < 2; mt++)
        #pragma unroll
        for (int nt = 0; nt < 8; nt++){
            int c = wn*64 + nt*8 + 2*p;
            #pragma unroll
            for (int h = 0; h < 2; h++){
                int row = wm*32 + mt*16 + q + h*8;
                bool okr = row < SEQ;
                float v0 = (okr && c   < SEQ) ? acc[mt][nt][2*h+0] * inv_n : 0.f;
                float v1 = (okr && c+1 < SEQ) ? acc[mt][nt][2*h+1] * inv_n : 0.f;
                rs[mt][h] += v0 + v1;
                bf16 h0, l0, h1, l1;
                split1(v0, h0, l0); split1(v1, h1, l1);
                size_t off = (size_t)row * 128 + c;
                *(__nv_bfloat162*)(Rh + off) = __nv_bfloat162(h0, h1);
                *(__nv_bfloat162*)(Rl + off) = __nv_bfloat162(l0, l1);
            }
        }
    #pragma unroll
    for (int mt = 0; mt < 2; mt++)
        #pragma unroll
        for (int h = 0; h < 2; h++){
            int row = wm*32 + mt*16 + q + h*8;
            atomicAdd(&s_sm[row], rs[mt][h]);
        }
    __syncthreads();
    if (tid < 128) g_S[b*128 + tid] = s_sm[tid];
}

// ---------------- attn_y: wy = R·g' + s·wgb + wb, BN, +resid ----------------
template<int LAST>
__global__ __launch_bounds__(256, 2)
void attn_y_bn(float* outp,
               const float* __restrict__ wgb_l, const float* __restrict__ wb,
               const float* __restrict__ gamma, const float* __restrict__ beta,
               const float* __restrict__ mean,  const float* __restrict__ var)
{
    extern __shared__ __align__(1024) char smem[];
    uint32_t sb = smem_u32(smem);
    int tid = threadIdx.x, wid = tid >> 5, lane = tid & 31;
    int b = blockIdx.y, n0 = blockIdx.x * 128;
    ZERO_ACC();

    auto stage_load = [&](int slot, int k0){
        uint32_t base = sb + slot * STG_B;
        #pragma unroll
        for (int i = 0; i < 4; i++){
            int cid = tid + i * 256;
            int row = cid >> 3, ch = cid & 7;
            const bf16* src = (ch < 4 ? g_Rh : g_Rl)
                + (size_t)b * 16384 + row * 128 + k0 + (ch & 3) * 8;
            uint32_t dst = base + row * 128 + ((ch ^ (row & 7)) << 4);
            CP16(dst, src);
        }
        #pragma unroll
        for (int i = 0; i < 4; i++){
            int cid = tid + i * 256;
            int buf = cid >> 9, rem = cid & 511;
            int k = rem >> 4, c = rem & 15;
            const bf16* src = (buf ? g_QKVl : g_QKVh)
                + (size_t)(b * SEQ + k0 + k) * NQKV + n0 + c * 8;
            uint32_t dst = base + 16384 + buf * 8192 + k * 256 + ((c ^ (k & 7)) << 4);
            CP16(dst, src);
        }
    };
    const int kiters = 4;
    #pragma unroll
    for (int s = 0; s < STAGES - 1; s++){ stage_load(s, s * 32); CPCOMMIT(); }

    int wm = wid >> 1, wn = wid & 1;
    int g = lane >> 3, r = lane & 7;
    int m = lane >> 3;

    for (int it = 0; it < kiters; it++){
        CPWAIT(STAGES - 2);
        __syncthreads();
        uint32_t sA = sb + (it % STAGES) * STG_B;
        NN_MAINLOOP_BODY(sA, sA + 16384);
        if (it + STAGES - 1 < kiters)
            stage_load((it + STAGES - 1) % STAGES, (it + STAGES - 1) * 32);
        CPCOMMIT();
    }
    CPWAIT(0);
    __syncthreads();
    float* cs = (float*)smem;
    float* cf = cs + 128;
    float* cw = cf + 128;
    if (tid < 128){
        int c = n0 + tid;
        float iv = gamma[c] * rsqrtf(var[c] + 1e-5f);
        cs[tid] = iv;
        cf[tid] = (wb[c] - mean[c]) * iv + beta[c];
        cw[tid] = wgb_l[c];      // raw wgb; iv applied once via cs below
    }
    __syncthreads();

    int q = lane >> 2, p = lane & 3;
    float sv[2][2];
    #pragma unroll
    for (int mt = 0; mt < 2; mt++)
        #pragma unroll
        for (int h = 0; h < 2; h++)
            sv[mt][h] = g_S[b*128 + wm*32 + mt*16 + q + h*8];

    #pragma unroll
    for (int mt = 0; mt < 2; mt++)
        #pragma unroll
        for (int nt = 0; nt < 8; nt++){
            int c = wn*64 + nt*8 + 2*p;
            #pragma unroll
            for (int h = 0; h < 2; h++){
                int row = wm*32 + mt*16 + q + h*8;
                if (row < SEQ){
                    size_t off = (size_t)(b*SEQ + row) * CH + n0 + c;
                    float2 rv = *(const float2*)(g_X + off);
                    float v0 = (acc[mt][nt][2*h+0] + sv[mt][h]*cw[c])   * cs[c]   + cf[c]   + rv.x;
                    float v1 = (acc[mt][nt][2*h+1] + sv[mt][h]*cw[c+1]) * cs[c+1] + cf[c+1] + rv.y;
                    // (acc + s*wgb + wb - mean)*iv + beta + resid
                    *(float2*)(outp + off) = make_float2(v0, v1);
                    if (!LAST){
                        bf16 h0, l0, h1, l1;
                        split1(v0, h0, l0); split1(v1, h1, l1);
                        *(__nv_bfloat162*)(g_Xh + off) = __nv_bfloat162(h0, h1);
                        *(__nv_bfloat162*)(g_Xl + off) = __nv_bfloat162(l0, l1);
                    }
                }
            }
        }
}

// ---------------- small prep kernels ----------------
__global__ void split_bf16(const float* __restrict__ in, bf16* __restrict__ hi,
                           bf16* __restrict__ lo, int n)
{
    int i = (blockIdx.x * blockDim.x + threadIdx.x) * 4;
    if (i < n){
        float4 x = *(const float4*)(in + i);
        bf16 h0,l0,h1,l1,h2,l2,h3,l3;
        split1(x.x,h0,l0); split1(x.y,h1,l1); split1(x.z,h2,l2); split1(x.w,h3,l3);
        *(__nv_bfloat162*)(hi + i)     = __nv_bfloat162(h0, h1);
        *(__nv_bfloat162*)(hi + i + 2) = __nv_bfloat162(h2, h3);
        *(__nv_bfloat162*)(lo + i)     = __nv_bfloat162(l0, l1);
        *(__nv_bfloat162*)(lo + i + 2) = __nv_bfloat162(l2, l3);
    }
}

__global__ void split_tp(const float* __restrict__ tw, const float* __restrict__ pw)
{
    int which = blockIdx.y;
    const float* src = which ? pw : tw;
    int i = (blockIdx.x * blockDim.x + threadIdx.x) * 4;
    if (i < LAYERS*CH*CH){
        int l = i / (CH*CH);
        int w = i - l * (CH*CH);
        size_t d = (size_t)WOFF_TP + (size_t)l * 2*CH*CH + (size_t)which * CH*CH + w;
        float4 x = *(const float4*)(src + i);
        bf16 h0,l0,h1,l1,h2,l2,h3,l3;
        split1(x.x,h0,l0); split1(x.y,h1,l1); split1(x.z,h2,l2); split1(x.w,h3,l3);
        *(__nv_bfloat162*)(g_Wh + d)     = __nv_bfloat162(h0, h1);
        *(__nv_bfloat162*)(g_Wh + d + 2) = __nv_bfloat162(h2, h3);
        *(__nv_bfloat162*)(g_Wl + d)     = __nv_bfloat162(l0, l1);
        *(__nv_bfloat162*)(g_Wl + d + 2) = __nv_bfloat162(l2, l3);
    }
}

__global__ void bias_fuse(const float* __restrict__ tb, const float* __restrict__ pb)
{
    int i = blockIdx.x * blockDim.x + threadIdx.x;
    if (i < LAYERS*NQKV){
        int l = i / NQKV, c = i % NQKV;
        float v = c < 512 ? 0.f : c < 1024 ? tb[l*512 + c - 512] : pb[l*512 + c - 1024];
        g_bqkv[i] = v;
    }
}

__global__ void wgb_k(const float* __restrict__ ww, const float* __restrict__ gb)
{
    int i = blockIdx.x * blockDim.x + threadIdx.x;
    if (i < LAYERS*CH){
        int l = i / CH, o = i % CH;
        const float4* w = (const float4*)(ww + (size_t)l*CH*CH + (size_t)o*CH);
        const float4* bsrc = (const float4*)(gb + l*CH);
        float s = 0.f;
        for (int k = 0; k < CH/4; k++){
            float4 a = w[k], c = bsrc[k];
            s += a.x*c.x + a.y*c.y + a.z*c.z + a.w*c.w;
        }
        g_wgb[i] = s;
    }
}

// ---------------- host ----------------
extern "C" void kernel_launch(void* const* d_in, const int* in_sizes, int n_in,
                              void* d_out, int out_size)
{
    (void)in_sizes; (void)n_in; (void)out_size;
    const float* img     = (const float*)d_in[0];
    const float* trans_w = (const float*)d_in[1];
    const float* trans_b = (const float*)d_in[2];
    const float* gw = (const float*)d_in[3];
    const float* gb = (const float*)d_in[4];
    const float* tw = (const float*)d_in[5];
    const float* tb = (const float*)d_in[6];
    const float* pw = (const float*)d_in[7];
    const float* pb = (const float*)d_in[8];
    const float* ww = (const float*)d_in[9];
    const float* wb = (const float*)d_in[10];
    const float* bn_gamma = (const float*)d_in[11];
    const float* bn_beta  = (const float*)d_in[12];
    const float* bn_mean  = (const float*)d_in[13];
    const float* bn_var   = (const float*)d_in[14];
    float* out = (float*)d_out;

    float *X, *bqkv, *wgbp;
    bf16 *Xh, *Xl, *Ih, *Il, *Wh, *Wl, *Vh, *Vl, *GWh, *GWl;
    cudaGetSymbolAddress((void**)&X,   g_X);
    cudaGetSymbolAddress((void**)&Xh,  g_Xh);
    cudaGetSymbolAddress((void**)&Xl,  g_Xl);
    cudaGetSymbolAddress((void**)&Ih,  g_Ih);
    cudaGetSymbolAddress((void**)&Il,  g_Il);
    cudaGetSymbolAddress((void**)&Wh,  g_Wh);
    cudaGetSymbolAddress((void**)&Wl,  g_Wl);
    cudaGetSymbolAddress((void**)&Vh,  g_Vh);
    cudaGetSymbolAddress((void**)&Vl,  g_Vl);
    cudaGetSymbolAddress((void**)&GWh, g_GWh);
    cudaGetSymbolAddress((void**)&GWl, g_GWl);
    cudaGetSymbolAddress((void**)&bqkv, g_bqkv);
    cudaGetSymbolAddress((void**)&wgbp, g_wgb);

    cudaFuncSetAttribute(enc_gemm,     cudaFuncAttributeMaxDynamicSharedMemorySize, SMEM_DYN);
    cudaFuncSetAttribute(qkv_gemm,     cudaFuncAttributeMaxDynamicSharedMemorySize, SMEM_DYN);
    cudaFuncSetAttribute(vgemm,        cudaFuncAttributeMaxDynamicSharedMemorySize, SMEM_DYN);
    cudaFuncSetAttribute(attn_r_mma,   cudaFuncAttributeMaxDynamicSharedMemorySize, SMEM_DYN);
    cudaFuncSetAttribute(attn_y_bn<0>, cudaFuncAttributeMaxDynamicSharedMemorySize, SMEM_DYN);
    cudaFuncSetAttribute(attn_y_bn<1>, cudaFuncAttributeMaxDynamicSharedMemorySize, SMEM_DYN);

    bias_fuse<<<(LAYERS*NQKV + 255)/256, 256>>>(tb, pb);
    wgb_k<<<(LAYERS*CH + 255)/256, 256>>>(ww, gb);
    {
        int n = MTOT*DIMIN;
        split_bf16<<<(n/4+255)/256, 256>>>(img, Ih, Il, n);
        n = WSZ_TRANS;
        split_bf16<<<(n/4+255)/256, 256>>>(trans_w, Wh+WOFF_TRANS, Wl+WOFF_TRANS, n);
        n = LAYERS*CH*CH;
        split_bf16<<<(n/4+255)/256, 256>>>(gw, GWh, GWl, n);
        split_tp<<<dim3((LAYERS*CH*CH/4+255)/256, 2), 256>>>(tw, pw);
        split_bf16<<<(n/4+255)/256, 256>>>(ww, Wh+WOFF_W, Wl+WOFF_W, n);
    }
    vgemm<<<dim3(4, 4, LAYERS), 256, SMEM_DYN>>>();

    // encoder: X = img @ trans_w^T + b (fp32 + split)
    enc_gemm<<<dim3(CH/128, MTOT/128), 256, SMEM_DYN>>>(
        Ih, Il, Wh+WOFF_TRANS, Wl+WOFF_TRANS, DIMIN, X, Xh, Xl, trans_b);

    for (int l = 0; l < LAYERS; l++){
        qkv_gemm<<<dim3(NQKV/128, MTOT/128), 256, SMEM_DYN>>>(
            Xh, Xl,
            Vh + (size_t)l*CH*CH, Vl + (size_t)l*CH*CH,
            Wh + WOFF_TP + (size_t)l*2*CH*CH, Wl + WOFF_TP + (size_t)l*2*CH*CH,
            bqkv + l*NQKV);

        attn_r_mma<<<BATCH, 256, SMEM_DYN>>>();

        if (l == LAYERS-1){
            attn_y_bn<1><<<dim3(CH/128, BATCH), 256, SMEM_DYN>>>(
                out, wgbp + l*CH, wb + l*CH,
                bn_gamma + l*CH, bn_beta + l*CH, bn_mean + l*CH, bn_var + l*CH);
        } else {
            attn_y_bn<0><<<dim3(CH/128, BATCH), 256, SMEM_DYN>>>(
                X, wgbp + l*CH, wb + l*CH,
                bn_gamma + l*CH, bn_beta + l*CH, bn_mean + l*CH, bn_var + l*CH);
        }
    }
}